// round 5
// baseline (speedup 1.0000x reference)
#include <cuda_runtime.h>
#include <cuda_bf16.h>
#include <cstdint>
#include <math.h>

// Problem constants (fixed by setup_inputs: B=1, T=8, H=16, W=32)
#define NTOK 4096
#define CDIM 2048
#define HEADS 16
#define HD 128

// ---------------- scratch (device globals; no allocations allowed) ----------
// split-bf16 representation: value ~= hi + lo (each bf16), ~17 mantissa bits
__device__ __nv_bfloat16 g_x_hi[NTOK * CDIM],  g_x_lo[NTOK * CDIM];
__device__ __nv_bfloat16 g_Wq_hi[CDIM * CDIM], g_Wq_lo[CDIM * CDIM];
__device__ __nv_bfloat16 g_Wk_hi[CDIM * CDIM], g_Wk_lo[CDIM * CDIM];
__device__ __nv_bfloat16 g_Wv_hi[CDIM * CDIM], g_Wv_lo[CDIM * CDIM];
__device__ __nv_bfloat16 g_Wo_hi[CDIM * CDIM], g_Wo_lo[CDIM * CDIM];
__device__ float g_qp[NTOK * CDIM];
__device__ float g_kp[NTOK * CDIM];
__device__ float g_vp[NTOK * CDIM];
// head-major [head][tok][hd], hi/lo pairs; q has 1/sqrt(HD) folded in
__device__ __nv_bfloat16 g_q_hi[NTOK * CDIM], g_q_lo[NTOK * CDIM];
__device__ __nv_bfloat16 g_k_hi[NTOK * CDIM], g_k_lo[NTOK * CDIM];
__device__ __nv_bfloat16 g_v_hi[NTOK * CDIM], g_v_lo[NTOK * CDIM];
// token-major attention output, hi/lo
__device__ __nv_bfloat16 g_ao_hi[NTOK * CDIM], g_ao_lo[NTOK * CDIM];

// ---------------- helpers ----------------------------------------------------
__device__ __forceinline__ void mma16816(float* c, const uint32_t* a, uint32_t b0, uint32_t b1) {
    asm volatile(
        "mma.sync.aligned.m16n8k16.row.col.f32.bf16.bf16.f32 "
        "{%0,%1,%2,%3}, {%4,%5,%6,%7}, {%8,%9}, {%0,%1,%2,%3};\n"
        : "+f"(c[0]), "+f"(c[1]), "+f"(c[2]), "+f"(c[3])
        : "r"(a[0]), "r"(a[1]), "r"(a[2]), "r"(a[3]), "r"(b0), "r"(b1));
}

__device__ __forceinline__ void split1(float x, __nv_bfloat16& h, __nv_bfloat16& l) {
    h = __float2bfloat16_rn(x);
    l = __float2bfloat16_rn(x - __bfloat162float(h));
}

// split two floats -> packed hi pair + packed lo pair
__device__ __forceinline__ void splitpack(float a, float b, uint32_t& hp, uint32_t& lp) {
    __nv_bfloat16 ha, la, hb, lb;
    split1(a, ha, la);
    split1(b, hb, lb);
    __nv_bfloat162 hh; hh.x = ha; hh.y = hb;
    __nv_bfloat162 ll; ll.x = la; ll.y = lb;
    hp = *reinterpret_cast<uint32_t*>(&hh);
    lp = *reinterpret_cast<uint32_t*>(&ll);
}

// ---------------- fp32 -> split-bf16 conversion -------------------------------
// SEL: 0=x, 1=Wq, 2=Wk, 3=Wv, 4=Wo
template <int SEL>
__global__ void split_bf16(const float* __restrict__ src, int n) {
    __nv_bfloat16* hi = (SEL == 0) ? g_x_hi : (SEL == 1) ? g_Wq_hi
                      : (SEL == 2) ? g_Wk_hi : (SEL == 3) ? g_Wv_hi : g_Wo_hi;
    __nv_bfloat16* lo = (SEL == 0) ? g_x_lo : (SEL == 1) ? g_Wq_lo
                      : (SEL == 2) ? g_Wk_lo : (SEL == 3) ? g_Wv_lo : g_Wo_lo;
    int i = (blockIdx.x * blockDim.x + threadIdx.x) * 4;
    if (i < n) {
        float4 v = *reinterpret_cast<const float4*>(src + i);
        uint32_t h0, l0, h1, l1;
        splitpack(v.x, v.y, h0, l0);
        splitpack(v.z, v.w, h1, l1);
        *reinterpret_cast<uint32_t*>(hi + i)     = h0;
        *reinterpret_cast<uint32_t*>(hi + i + 2) = h1;
        *reinterpret_cast<uint32_t*>(lo + i)     = l0;
        *reinterpret_cast<uint32_t*>(lo + i + 2) = l1;
    }
}

// ---------------- split GEMM: C[m][n] = sum_k A[m][k]*B[n][k] + bias[n] ------
// 3-term: Ah*Bh + Ah*Bl + Al*Bh, fp32 accumulate.
// SEL: 0=Q, 1=K, 2=V (A=x), 3=O (A=ao, C=outp). M=NTOK, N=K=CDIM.
template <int SEL>
__global__ __launch_bounds__(256) void gemm_split(const float* __restrict__ bias,
                                                  float* __restrict__ outp)
{
    const __nv_bfloat16* __restrict__ Ah = (SEL == 3) ? g_ao_hi : g_x_hi;
    const __nv_bfloat16* __restrict__ Al = (SEL == 3) ? g_ao_lo : g_x_lo;
    const __nv_bfloat16* __restrict__ Bh = (SEL == 0) ? g_Wq_hi : (SEL == 1) ? g_Wk_hi
                                         : (SEL == 2) ? g_Wv_hi : g_Wo_hi;
    const __nv_bfloat16* __restrict__ Bl = (SEL == 0) ? g_Wq_lo : (SEL == 1) ? g_Wk_lo
                                         : (SEL == 2) ? g_Wv_lo : g_Wo_lo;
    float* __restrict__ Cout = (SEL == 0) ? g_qp : (SEL == 1) ? g_kp
                             : (SEL == 2) ? g_vp : outp;
    const int Kd = CDIM, N = CDIM;

    __shared__ __nv_bfloat16 sA[2][128][40];   // [hi/lo][row][kcol]
    __shared__ __nv_bfloat16 sB[2][128][40];
    const int tid = threadIdx.x, lane = tid & 31, warp = tid >> 5;
    const int wm = warp >> 2, wn = warp & 3;     // 2x4 warp grid, 64x32 warp tile
    const int m0 = blockIdx.y * 128, n0 = blockIdx.x * 128;
    const int g = lane >> 2, cc2 = (lane & 3) * 2;
    float acc[4][4][4] = {};

    // load tile 0 (1024 uint2 slots per array; 4 per thread)
    #pragma unroll
    for (int i = 0; i < 4; i++) {
        int c = tid + i * 256; int row = c >> 3; int col = (c & 7) * 4;
        size_t ga = (size_t)(m0 + row) * Kd + col;
        size_t gb = (size_t)(n0 + row) * Kd + col;
        *reinterpret_cast<uint2*>(&sA[0][row][col]) = *reinterpret_cast<const uint2*>(Ah + ga);
        *reinterpret_cast<uint2*>(&sA[1][row][col]) = *reinterpret_cast<const uint2*>(Al + ga);
        *reinterpret_cast<uint2*>(&sB[0][row][col]) = *reinterpret_cast<const uint2*>(Bh + gb);
        *reinterpret_cast<uint2*>(&sB[1][row][col]) = *reinterpret_cast<const uint2*>(Bl + gb);
    }
    __syncthreads();

    const int NKT = Kd / 32;   // 64
    for (int kt = 0; kt < NKT; kt++) {
        uint2 rah[4], ral[4], rbh[4], rbl[4];
        if (kt + 1 < NKT) {
            #pragma unroll
            for (int i = 0; i < 4; i++) {
                int c = tid + i * 256; int row = c >> 3; int col = (c & 7) * 4;
                size_t ga = (size_t)(m0 + row) * Kd + (kt + 1) * 32 + col;
                size_t gb = (size_t)(n0 + row) * Kd + (kt + 1) * 32 + col;
                rah[i] = *reinterpret_cast<const uint2*>(Ah + ga);
                ral[i] = *reinterpret_cast<const uint2*>(Al + ga);
                rbh[i] = *reinterpret_cast<const uint2*>(Bh + gb);
                rbl[i] = *reinterpret_cast<const uint2*>(Bl + gb);
            }
        }
        #pragma unroll
        for (int ks = 0; ks < 2; ks++) {
            uint32_t ah[4][4], al[4][4];
            #pragma unroll
            for (int mf = 0; mf < 4; mf++) {
                int r = wm * 64 + mf * 16 + g;
                ah[mf][0] = *reinterpret_cast<const uint32_t*>(&sA[0][r][ks * 16 + cc2]);
                ah[mf][1] = *reinterpret_cast<const uint32_t*>(&sA[0][r + 8][ks * 16 + cc2]);
                ah[mf][2] = *reinterpret_cast<const uint32_t*>(&sA[0][r][ks * 16 + cc2 + 8]);
                ah[mf][3] = *reinterpret_cast<const uint32_t*>(&sA[0][r + 8][ks * 16 + cc2 + 8]);
                al[mf][0] = *reinterpret_cast<const uint32_t*>(&sA[1][r][ks * 16 + cc2]);
                al[mf][1] = *reinterpret_cast<const uint32_t*>(&sA[1][r + 8][ks * 16 + cc2]);
                al[mf][2] = *reinterpret_cast<const uint32_t*>(&sA[1][r][ks * 16 + cc2 + 8]);
                al[mf][3] = *reinterpret_cast<const uint32_t*>(&sA[1][r + 8][ks * 16 + cc2 + 8]);
            }
            #pragma unroll
            for (int nf = 0; nf < 4; nf++) {
                int r = wn * 32 + nf * 8 + g;
                uint32_t bh0 = *reinterpret_cast<const uint32_t*>(&sB[0][r][ks * 16 + cc2]);
                uint32_t bh1 = *reinterpret_cast<const uint32_t*>(&sB[0][r][ks * 16 + cc2 + 8]);
                uint32_t bl0 = *reinterpret_cast<const uint32_t*>(&sB[1][r][ks * 16 + cc2]);
                uint32_t bl1 = *reinterpret_cast<const uint32_t*>(&sB[1][r][ks * 16 + cc2 + 8]);
                #pragma unroll
                for (int mf = 0; mf < 4; mf++) {
                    mma16816(acc[mf][nf], ah[mf], bh0, bh1);
                    mma16816(acc[mf][nf], ah[mf], bl0, bl1);
                    mma16816(acc[mf][nf], al[mf], bh0, bh1);
                }
            }
        }
        __syncthreads();
        if (kt + 1 < NKT) {
            #pragma unroll
            for (int i = 0; i < 4; i++) {
                int c = tid + i * 256; int row = c >> 3; int col = (c & 7) * 4;
                *reinterpret_cast<uint2*>(&sA[0][row][col]) = rah[i];
                *reinterpret_cast<uint2*>(&sA[1][row][col]) = ral[i];
                *reinterpret_cast<uint2*>(&sB[0][row][col]) = rbh[i];
                *reinterpret_cast<uint2*>(&sB[1][row][col]) = rbl[i];
            }
        }
        __syncthreads();
    }

    #pragma unroll
    for (int mf = 0; mf < 4; mf++) {
        int r0 = m0 + wm * 64 + mf * 16 + g;
        #pragma unroll
        for (int nf = 0; nf < 4; nf++) {
            int col = n0 + wn * 32 + nf * 8 + cc2;
            float b0v = bias[col], b1v = bias[col + 1];
            Cout[(size_t)r0 * N + col]           = acc[mf][nf][0] + b0v;
            Cout[(size_t)r0 * N + col + 1]       = acc[mf][nf][1] + b1v;
            Cout[(size_t)(r0 + 8) * N + col]     = acc[mf][nf][2] + b0v;
            Cout[(size_t)(r0 + 8) * N + col + 1] = acc[mf][nf][3] + b1v;
        }
    }
}

// ---------------- RMSNorm + 3D RoPE + split + pack ---------------------------
// HD=128: dt=44 (22 pairs), dh=42 (21 pairs), dw=42 (21 pairs); T=8,H=16,W=32
__device__ __forceinline__ float rope_ang(int p, int token) {
    int t = token >> 9;          // / (16*32)
    int rem = token & 511;
    int h = rem >> 5, w = rem & 31;
    float pos, expo, d;
    if (p < 22)      { pos = (float)t; expo = (float)(2 * p);        d = 44.f; }
    else if (p < 43) { pos = (float)h; expo = (float)(2 * (p - 22)); d = 42.f; }
    else             { pos = (float)w; expo = (float)(2 * (p - 43)); d = 42.f; }
    return pos * powf(10000.f, -expo / d);
}

__global__ __launch_bounds__(128) void normrope(const float* __restrict__ qnw,
                                                const float* __restrict__ knw) {
    int idx = blockIdx.x * 4 + (threadIdx.x >> 5);   // (token,head) id
    int lane = threadIdx.x & 31;
    int token = idx >> 4, head = idx & 15;
    int base = token * CDIM + head * HD;
    int e = lane * 4;
    const float SC = 0.08838834764831845f;  // 1/sqrt(128), folded into q

    float ang0 = rope_ang(lane * 2, token);
    float ang1 = rope_ang(lane * 2 + 1, token);
    float co0 = cosf(ang0), si0 = sinf(ang0);
    float co1 = cosf(ang1), si1 = sinf(ang1);
    int ob = (head * NTOK + token) * HD + e;

    // Q (rmsnorm + rope + scale + split)
    {
        float4 q = *reinterpret_cast<const float4*>(&g_qp[base + e]);
        float ss = q.x * q.x + q.y * q.y + q.z * q.z + q.w * q.w;
        #pragma unroll
        for (int o = 16; o; o >>= 1) ss += __shfl_xor_sync(0xffffffffu, ss, o);
        float r = rsqrtf(ss * (1.f / 128.f) + 1e-6f);
        float a0 = q.x * r * qnw[e], a1 = q.y * r * qnw[e + 1];
        float a2 = q.z * r * qnw[e + 2], a3 = q.w * r * qnw[e + 3];
        float o0 = (a0 * co0 - a1 * si0) * SC, o1 = (a0 * si0 + a1 * co0) * SC;
        float o2 = (a2 * co1 - a3 * si1) * SC, o3 = (a2 * si1 + a3 * co1) * SC;
        uint32_t h0, l0, h1, l1;
        splitpack(o0, o1, h0, l0);
        splitpack(o2, o3, h1, l1);
        *reinterpret_cast<uint32_t*>(&g_q_hi[ob])     = h0;
        *reinterpret_cast<uint32_t*>(&g_q_hi[ob + 2]) = h1;
        *reinterpret_cast<uint32_t*>(&g_q_lo[ob])     = l0;
        *reinterpret_cast<uint32_t*>(&g_q_lo[ob + 2]) = l1;
    }
    // K (rmsnorm + rope + split)
    {
        float4 k = *reinterpret_cast<const float4*>(&g_kp[base + e]);
        float ss = k.x * k.x + k.y * k.y + k.z * k.z + k.w * k.w;
        #pragma unroll
        for (int o = 16; o; o >>= 1) ss += __shfl_xor_sync(0xffffffffu, ss, o);
        float r = rsqrtf(ss * (1.f / 128.f) + 1e-6f);
        float a0 = k.x * r * knw[e], a1 = k.y * r * knw[e + 1];
        float a2 = k.z * r * knw[e + 2], a3 = k.w * r * knw[e + 3];
        float o0 = a0 * co0 - a1 * si0, o1 = a0 * si0 + a1 * co0;
        float o2 = a2 * co1 - a3 * si1, o3 = a2 * si1 + a3 * co1;
        uint32_t h0, l0, h1, l1;
        splitpack(o0, o1, h0, l0);
        splitpack(o2, o3, h1, l1);
        *reinterpret_cast<uint32_t*>(&g_k_hi[ob])     = h0;
        *reinterpret_cast<uint32_t*>(&g_k_hi[ob + 2]) = h1;
        *reinterpret_cast<uint32_t*>(&g_k_lo[ob])     = l0;
        *reinterpret_cast<uint32_t*>(&g_k_lo[ob + 2]) = l1;
    }
    // V (split only)
    {
        float4 v = *reinterpret_cast<const float4*>(&g_vp[base + e]);
        uint32_t h0, l0, h1, l1;
        splitpack(v.x, v.y, h0, l0);
        splitpack(v.z, v.w, h1, l1);
        *reinterpret_cast<uint32_t*>(&g_v_hi[ob])     = h0;
        *reinterpret_cast<uint32_t*>(&g_v_hi[ob + 2]) = h1;
        *reinterpret_cast<uint32_t*>(&g_v_lo[ob])     = l0;
        *reinterpret_cast<uint32_t*>(&g_v_lo[ob + 2]) = l1;
    }
}

// ---------------- Flash attention (64q tile, 32-key tiles, split-bf16) -------
__global__ __launch_bounds__(128) void attn_kernel() {
    const int head = blockIdx.y;
    const int qb = blockIdx.x * 64;
    const int tid = threadIdx.x, lane = tid & 31, warp = tid >> 5;
    const int g = lane >> 2, cc2 = (lane & 3) * 2;
    const size_t hb = (size_t)head * NTOK * HD;
    const __nv_bfloat16* Qh = g_q_hi + hb;
    const __nv_bfloat16* Ql = g_q_lo + hb;
    const __nv_bfloat16* Kh = g_k_hi + hb;
    const __nv_bfloat16* Kl = g_k_lo + hb;
    const __nv_bfloat16* Vh = g_v_hi + hb;
    const __nv_bfloat16* Vl = g_v_lo + hb;

    __shared__ __nv_bfloat16 sK[2][32][136];    // [hi/lo][key][d]
    __shared__ __nv_bfloat16 sVt[2][128][40];   // [hi/lo][d][key]

    const int r0 = qb + warp * 16 + g;
    uint32_t qah[8][4], qal[8][4];
    #pragma unroll
    for (int ks = 0; ks < 8; ks++) {
        qah[ks][0] = *reinterpret_cast<const uint32_t*>(&Qh[(size_t)r0 * HD + ks * 16 + cc2]);
        qah[ks][1] = *reinterpret_cast<const uint32_t*>(&Qh[(size_t)(r0 + 8) * HD + ks * 16 + cc2]);
        qah[ks][2] = *reinterpret_cast<const uint32_t*>(&Qh[(size_t)r0 * HD + ks * 16 + cc2 + 8]);
        qah[ks][3] = *reinterpret_cast<const uint32_t*>(&Qh[(size_t)(r0 + 8) * HD + ks * 16 + cc2 + 8]);
        qal[ks][0] = *reinterpret_cast<const uint32_t*>(&Ql[(size_t)r0 * HD + ks * 16 + cc2]);
        qal[ks][1] = *reinterpret_cast<const uint32_t*>(&Ql[(size_t)(r0 + 8) * HD + ks * 16 + cc2]);
        qal[ks][2] = *reinterpret_cast<const uint32_t*>(&Ql[(size_t)r0 * HD + ks * 16 + cc2 + 8]);
        qal[ks][3] = *reinterpret_cast<const uint32_t*>(&Ql[(size_t)(r0 + 8) * HD + ks * 16 + cc2 + 8]);
    }

    float o[16][4] = {};
    float m0v = -1e30f, m1v = -1e30f, l0 = 0.f, l1 = 0.f;

    for (int kt = 0; kt < NTOK / 32; kt++) {
        int kbase = kt * 32;
        #pragma unroll
        for (int i = 0; i < 8; i++) {       // 32x128 tiles: 1024 uint2 slots
            int c = tid + i * 128; int row = c >> 5; int col = (c & 31) * 4;
            size_t ga = (size_t)(kbase + row) * HD + col;
            *reinterpret_cast<uint2*>(&sK[0][row][col]) = *reinterpret_cast<const uint2*>(Kh + ga);
            *reinterpret_cast<uint2*>(&sK[1][row][col]) = *reinterpret_cast<const uint2*>(Kl + ga);
            uint2 vh = *reinterpret_cast<const uint2*>(Vh + ga);
            uint2 vl = *reinterpret_cast<const uint2*>(Vl + ga);
            __nv_bfloat16 th[4]; *reinterpret_cast<uint2*>(th) = vh;
            __nv_bfloat16 tl[4]; *reinterpret_cast<uint2*>(tl) = vl;
            sVt[0][col][row] = th[0]; sVt[0][col + 1][row] = th[1];
            sVt[0][col + 2][row] = th[2]; sVt[0][col + 3][row] = th[3];
            sVt[1][col][row] = tl[0]; sVt[1][col + 1][row] = tl[1];
            sVt[1][col + 2][row] = tl[2]; sVt[1][col + 3][row] = tl[3];
        }
        __syncthreads();

        float s[4][4] = {};
        #pragma unroll
        for (int ks = 0; ks < 8; ks++) {
            #pragma unroll
            for (int nf = 0; nf < 4; nf++) {
                int r = nf * 8 + g;
                uint32_t bh0 = *reinterpret_cast<const uint32_t*>(&sK[0][r][ks * 16 + cc2]);
                uint32_t bh1 = *reinterpret_cast<const uint32_t*>(&sK[0][r][ks * 16 + cc2 + 8]);
                uint32_t bl0 = *reinterpret_cast<const uint32_t*>(&sK[1][r][ks * 16 + cc2]);
                uint32_t bl1 = *reinterpret_cast<const uint32_t*>(&sK[1][r][ks * 16 + cc2 + 8]);
                mma16816(s[nf], qah[ks], bh0, bh1);
                mma16816(s[nf], qah[ks], bl0, bl1);
                mma16816(s[nf], qal[ks], bh0, bh1);
            }
        }

        // online softmax over this 32-key stripe (scale pre-folded into q)
        float mx0 = -1e30f, mx1 = -1e30f;
        #pragma unroll
        for (int nf = 0; nf < 4; nf++) {
            mx0 = fmaxf(mx0, fmaxf(s[nf][0], s[nf][1]));
            mx1 = fmaxf(mx1, fmaxf(s[nf][2], s[nf][3]));
        }
        mx0 = fmaxf(mx0, __shfl_xor_sync(0xffffffffu, mx0, 1));
        mx0 = fmaxf(mx0, __shfl_xor_sync(0xffffffffu, mx0, 2));
        mx1 = fmaxf(mx1, __shfl_xor_sync(0xffffffffu, mx1, 1));
        mx1 = fmaxf(mx1, __shfl_xor_sync(0xffffffffu, mx1, 2));
        float nm0 = fmaxf(m0v, mx0), nm1 = fmaxf(m1v, mx1);
        float c0 = __expf(m0v - nm0), c1 = __expf(m1v - nm1);
        m0v = nm0; m1v = nm1;

        float rs0 = 0.f, rs1 = 0.f;
        #pragma unroll
        for (int nf = 0; nf < 4; nf++) {
            s[nf][0] = __expf(s[nf][0] - nm0); s[nf][1] = __expf(s[nf][1] - nm0);
            s[nf][2] = __expf(s[nf][2] - nm1); s[nf][3] = __expf(s[nf][3] - nm1);
            rs0 += s[nf][0] + s[nf][1];
            rs1 += s[nf][2] + s[nf][3];
        }
        rs0 += __shfl_xor_sync(0xffffffffu, rs0, 1);
        rs0 += __shfl_xor_sync(0xffffffffu, rs0, 2);
        rs1 += __shfl_xor_sync(0xffffffffu, rs1, 1);
        rs1 += __shfl_xor_sync(0xffffffffu, rs1, 2);
        l0 = l0 * c0 + rs0; l1 = l1 * c1 + rs1;
        #pragma unroll
        for (int nf = 0; nf < 16; nf++) {
            o[nf][0] *= c0; o[nf][1] *= c0; o[nf][2] *= c1; o[nf][3] *= c1;
        }

        // split P into hi/lo fragments
        uint32_t pah[2][4], pal[2][4];
        #pragma unroll
        for (int kk = 0; kk < 2; kk++) {
            splitpack(s[2 * kk][0],     s[2 * kk][1],     pah[kk][0], pal[kk][0]);
            splitpack(s[2 * kk][2],     s[2 * kk][3],     pah[kk][1], pal[kk][1]);
            splitpack(s[2 * kk + 1][0], s[2 * kk + 1][1], pah[kk][2], pal[kk][2]);
            splitpack(s[2 * kk + 1][2], s[2 * kk + 1][3], pah[kk][3], pal[kk][3]);
        }
        #pragma unroll
        for (int kk = 0; kk < 2; kk++) {
            #pragma unroll
            for (int nf = 0; nf < 16; nf++) {
                int d = nf * 8 + g;
                uint32_t bh0 = *reinterpret_cast<const uint32_t*>(&sVt[0][d][kk * 16 + cc2]);
                uint32_t bh1 = *reinterpret_cast<const uint32_t*>(&sVt[0][d][kk * 16 + cc2 + 8]);
                uint32_t bl0 = *reinterpret_cast<const uint32_t*>(&sVt[1][d][kk * 16 + cc2]);
                uint32_t bl1 = *reinterpret_cast<const uint32_t*>(&sVt[1][d][kk * 16 + cc2 + 8]);
                mma16816(o[nf], pah[kk], bh0, bh1);
                mma16816(o[nf], pah[kk], bl0, bl1);
                mma16816(o[nf], pal[kk], bh0, bh1);
            }
        }
        __syncthreads();
    }

    float i0 = 1.f / l0, i1 = 1.f / l1;
    #pragma unroll
    for (int nf = 0; nf < 16; nf++) {
        int col = head * HD + nf * 8 + cc2;
        uint32_t h0, lo0, h1, lo1;
        splitpack(o[nf][0] * i0, o[nf][1] * i0, h0, lo0);
        splitpack(o[nf][2] * i1, o[nf][3] * i1, h1, lo1);
        *reinterpret_cast<uint32_t*>(&g_ao_hi[(size_t)r0 * CDIM + col])       = h0;
        *reinterpret_cast<uint32_t*>(&g_ao_lo[(size_t)r0 * CDIM + col])       = lo0;
        *reinterpret_cast<uint32_t*>(&g_ao_hi[(size_t)(r0 + 8) * CDIM + col]) = h1;
        *reinterpret_cast<uint32_t*>(&g_ao_lo[(size_t)(r0 + 8) * CDIM + col]) = lo1;
    }
}

// ---------------- launch ------------------------------------------------------
extern "C" void kernel_launch(void* const* d_in, const int* in_sizes, int n_in,
                              void* d_out, int out_size) {
    const float* x   = (const float*)d_in[0];
    const float* Wq  = (const float*)d_in[1];
    const float* bq  = (const float*)d_in[2];
    const float* Wk  = (const float*)d_in[3];
    const float* bk  = (const float*)d_in[4];
    const float* Wv  = (const float*)d_in[5];
    const float* bv  = (const float*)d_in[6];
    const float* qnw = (const float*)d_in[7];
    const float* knw = (const float*)d_in[8];
    const float* Wo  = (const float*)d_in[9];
    const float* bo  = (const float*)d_in[10];
    float* out = (float*)d_out;

    const int NW = CDIM * CDIM;   // 4194304
    const int NX = NTOK * CDIM;   // 8388608
    split_bf16<0><<<NX / 1024, 256>>>(x, NX);
    split_bf16<1><<<NW / 1024, 256>>>(Wq, NW);
    split_bf16<2><<<NW / 1024, 256>>>(Wk, NW);
    split_bf16<3><<<NW / 1024, 256>>>(Wv, NW);
    split_bf16<4><<<NW / 1024, 256>>>(Wo, NW);

    dim3 ggrid(CDIM / 128, NTOK / 128);
    gemm_split<0><<<ggrid, 256>>>(bq, nullptr);
    gemm_split<1><<<ggrid, 256>>>(bk, nullptr);
    gemm_split<2><<<ggrid, 256>>>(bv, nullptr);

    normrope<<<NTOK * HEADS / 4, 128>>>(qnw, knw);

    dim3 agrid(NTOK / 64, HEADS);
    attn_kernel<<<agrid, 128>>>();

    gemm_split<3><<<ggrid, 256>>>(bo, out);
}

// round 9
// speedup vs baseline: 1.2316x; 1.2316x over previous
#include <cuda_runtime.h>
#include <cuda_bf16.h>
#include <cstdint>
#include <math.h>

// Problem constants (fixed by setup_inputs: B=1, T=8, H=16, W=32)
#define NTOK 4096
#define CDIM 2048
#define HEADS 16
#define HD 128

// ---------------- scratch (device globals; no allocations allowed) ----------
__device__ __nv_bfloat16 g_x_hi[NTOK * CDIM],  g_x_lo[NTOK * CDIM];
__device__ __nv_bfloat16 g_Wq_hi[CDIM * CDIM], g_Wq_lo[CDIM * CDIM];
__device__ __nv_bfloat16 g_Wk_hi[CDIM * CDIM], g_Wk_lo[CDIM * CDIM];
__device__ __nv_bfloat16 g_Wv_hi[CDIM * CDIM], g_Wv_lo[CDIM * CDIM];
__device__ __nv_bfloat16 g_Wo_hi[CDIM * CDIM], g_Wo_lo[CDIM * CDIM];
__device__ float g_qp[NTOK * CDIM];
__device__ float g_kp[NTOK * CDIM];
__device__ float g_vp[NTOK * CDIM];
__device__ __nv_bfloat16 g_q_hi[NTOK * CDIM], g_q_lo[NTOK * CDIM];
__device__ __nv_bfloat16 g_k_hi[NTOK * CDIM], g_k_lo[NTOK * CDIM];
__device__ __nv_bfloat16 g_v_hi[NTOK * CDIM], g_v_lo[NTOK * CDIM];
__device__ __nv_bfloat16 g_ao_hi[NTOK * CDIM], g_ao_lo[NTOK * CDIM];

// ---------------- helpers ----------------------------------------------------
__device__ __forceinline__ void mma16816(float* c, const uint32_t* a, uint32_t b0, uint32_t b1) {
    asm volatile(
        "mma.sync.aligned.m16n8k16.row.col.f32.bf16.bf16.f32 "
        "{%0,%1,%2,%3}, {%4,%5,%6,%7}, {%8,%9}, {%0,%1,%2,%3};\n"
        : "+f"(c[0]), "+f"(c[1]), "+f"(c[2]), "+f"(c[3])
        : "r"(a[0]), "r"(a[1]), "r"(a[2]), "r"(a[3]), "r"(b0), "r"(b1));
}

__device__ __forceinline__ void split1(float x, __nv_bfloat16& h, __nv_bfloat16& l) {
    h = __float2bfloat16_rn(x);
    l = __float2bfloat16_rn(x - __bfloat162float(h));
}

__device__ __forceinline__ void splitpack(float a, float b, uint32_t& hp, uint32_t& lp) {
    __nv_bfloat16 ha, la, hb, lb;
    split1(a, ha, la);
    split1(b, hb, lb);
    __nv_bfloat162 hh; hh.x = ha; hh.y = hb;
    __nv_bfloat162 ll; ll.x = la; ll.y = lb;
    hp = *reinterpret_cast<uint32_t*>(&hh);
    lp = *reinterpret_cast<uint32_t*>(&ll);
}

// ---------------- fp32 -> split-bf16 conversion -------------------------------
template <int SEL>
__global__ void split_bf16(const float* __restrict__ src, int n) {
    __nv_bfloat16* hi = (SEL == 0) ? g_x_hi : (SEL == 1) ? g_Wq_hi
                      : (SEL == 2) ? g_Wk_hi : (SEL == 3) ? g_Wv_hi : g_Wo_hi;
    __nv_bfloat16* lo = (SEL == 0) ? g_x_lo : (SEL == 1) ? g_Wq_lo
                      : (SEL == 2) ? g_Wk_lo : (SEL == 3) ? g_Wv_lo : g_Wo_lo;
    int i = (blockIdx.x * blockDim.x + threadIdx.x) * 4;
    if (i < n) {
        float4 v = *reinterpret_cast<const float4*>(src + i);
        uint32_t h0, l0, h1, l1;
        splitpack(v.x, v.y, h0, l0);
        splitpack(v.z, v.w, h1, l1);
        *reinterpret_cast<uint32_t*>(hi + i)     = h0;
        *reinterpret_cast<uint32_t*>(hi + i + 2) = h1;
        *reinterpret_cast<uint32_t*>(lo + i)     = l0;
        *reinterpret_cast<uint32_t*>(lo + i + 2) = l1;
    }
}

// ---------------- split GEMM (round-5 proven version) -------------------------
// C[m][n] = sum_k A[m][k]*B[n][k] + bias[n]; 3-term split-bf16, fp32 accum.
// SEL: 0=Q, 1=K, 2=V (A=x), 3=O (A=ao, C=outp). M=NTOK, N=K=CDIM.
template <int SEL>
__global__ __launch_bounds__(256) void gemm_split(const float* __restrict__ bias,
                                                  float* __restrict__ outp)
{
    const __nv_bfloat16* __restrict__ Ah = (SEL == 3) ? g_ao_hi : g_x_hi;
    const __nv_bfloat16* __restrict__ Al = (SEL == 3) ? g_ao_lo : g_x_lo;
    const __nv_bfloat16* __restrict__ Bh = (SEL == 0) ? g_Wq_hi : (SEL == 1) ? g_Wk_hi
                                         : (SEL == 2) ? g_Wv_hi : g_Wo_hi;
    const __nv_bfloat16* __restrict__ Bl = (SEL == 0) ? g_Wq_lo : (SEL == 1) ? g_Wk_lo
                                         : (SEL == 2) ? g_Wv_lo : g_Wo_lo;
    float* __restrict__ Cout = (SEL == 0) ? g_qp : (SEL == 1) ? g_kp
                             : (SEL == 2) ? g_vp : outp;
    const int Kd = CDIM, N = CDIM;

    __shared__ __nv_bfloat16 sA[2][128][40];   // [hi/lo][row][kcol]
    __shared__ __nv_bfloat16 sB[2][128][40];
    const int tid = threadIdx.x, lane = tid & 31, warp = tid >> 5;
    const int wm = warp >> 2, wn = warp & 3;     // 2x4 warp grid, 64x32 warp tile
    const int m0 = blockIdx.y * 128, n0 = blockIdx.x * 128;
    const int g = lane >> 2, cc2 = (lane & 3) * 2;
    float acc[4][4][4] = {};

    // load tile 0 (1024 uint2 slots per array; 4 per thread)
    #pragma unroll
    for (int i = 0; i < 4; i++) {
        int c = tid + i * 256; int row = c >> 3; int col = (c & 7) * 4;
        size_t ga = (size_t)(m0 + row) * Kd + col;
        size_t gb = (size_t)(n0 + row) * Kd + col;
        *reinterpret_cast<uint2*>(&sA[0][row][col]) = *reinterpret_cast<const uint2*>(Ah + ga);
        *reinterpret_cast<uint2*>(&sA[1][row][col]) = *reinterpret_cast<const uint2*>(Al + ga);
        *reinterpret_cast<uint2*>(&sB[0][row][col]) = *reinterpret_cast<const uint2*>(Bh + gb);
        *reinterpret_cast<uint2*>(&sB[1][row][col]) = *reinterpret_cast<const uint2*>(Bl + gb);
    }
    __syncthreads();

    const int NKT = Kd / 32;   // 64
    for (int kt = 0; kt < NKT; kt++) {
        uint2 rah[4], ral[4], rbh[4], rbl[4];
        if (kt + 1 < NKT) {
            #pragma unroll
            for (int i = 0; i < 4; i++) {
                int c = tid + i * 256; int row = c >> 3; int col = (c & 7) * 4;
                size_t ga = (size_t)(m0 + row) * Kd + (kt + 1) * 32 + col;
                size_t gb = (size_t)(n0 + row) * Kd + (kt + 1) * 32 + col;
                rah[i] = *reinterpret_cast<const uint2*>(Ah + ga);
                ral[i] = *reinterpret_cast<const uint2*>(Al + ga);
                rbh[i] = *reinterpret_cast<const uint2*>(Bh + gb);
                rbl[i] = *reinterpret_cast<const uint2*>(Bl + gb);
            }
        }
        #pragma unroll
        for (int ks = 0; ks < 2; ks++) {
            uint32_t ah[4][4], al[4][4];
            #pragma unroll
            for (int mf = 0; mf < 4; mf++) {
                int r = wm * 64 + mf * 16 + g;
                ah[mf][0] = *reinterpret_cast<const uint32_t*>(&sA[0][r][ks * 16 + cc2]);
                ah[mf][1] = *reinterpret_cast<const uint32_t*>(&sA[0][r + 8][ks * 16 + cc2]);
                ah[mf][2] = *reinterpret_cast<const uint32_t*>(&sA[0][r][ks * 16 + cc2 + 8]);
                ah[mf][3] = *reinterpret_cast<const uint32_t*>(&sA[0][r + 8][ks * 16 + cc2 + 8]);
                al[mf][0] = *reinterpret_cast<const uint32_t*>(&sA[1][r][ks * 16 + cc2]);
                al[mf][1] = *reinterpret_cast<const uint32_t*>(&sA[1][r + 8][ks * 16 + cc2]);
                al[mf][2] = *reinterpret_cast<const uint32_t*>(&sA[1][r][ks * 16 + cc2 + 8]);
                al[mf][3] = *reinterpret_cast<const uint32_t*>(&sA[1][r + 8][ks * 16 + cc2 + 8]);
            }
            #pragma unroll
            for (int nf = 0; nf < 4; nf++) {
                int r = wn * 32 + nf * 8 + g;
                uint32_t bh0 = *reinterpret_cast<const uint32_t*>(&sB[0][r][ks * 16 + cc2]);
                uint32_t bh1 = *reinterpret_cast<const uint32_t*>(&sB[0][r][ks * 16 + cc2 + 8]);
                uint32_t bl0 = *reinterpret_cast<const uint32_t*>(&sB[1][r][ks * 16 + cc2]);
                uint32_t bl1 = *reinterpret_cast<const uint32_t*>(&sB[1][r][ks * 16 + cc2 + 8]);
                #pragma unroll
                for (int mf = 0; mf < 4; mf++) {
                    mma16816(acc[mf][nf], ah[mf], bh0, bh1);
                    mma16816(acc[mf][nf], ah[mf], bl0, bl1);
                    mma16816(acc[mf][nf], al[mf], bh0, bh1);
                }
            }
        }
        __syncthreads();
        if (kt + 1 < NKT) {
            #pragma unroll
            for (int i = 0; i < 4; i++) {
                int c = tid + i * 256; int row = c >> 3; int col = (c & 7) * 4;
                *reinterpret_cast<uint2*>(&sA[0][row][col]) = rah[i];
                *reinterpret_cast<uint2*>(&sA[1][row][col]) = ral[i];
                *reinterpret_cast<uint2*>(&sB[0][row][col]) = rbh[i];
                *reinterpret_cast<uint2*>(&sB[1][row][col]) = rbl[i];
            }
        }
        __syncthreads();
    }

    #pragma unroll
    for (int mf = 0; mf < 4; mf++) {
        int r0 = m0 + wm * 64 + mf * 16 + g;
        #pragma unroll
        for (int nf = 0; nf < 4; nf++) {
            int col = n0 + wn * 32 + nf * 8 + cc2;
            float b0v = bias[col], b1v = bias[col + 1];
            Cout[(size_t)r0 * N + col]           = acc[mf][nf][0] + b0v;
            Cout[(size_t)r0 * N + col + 1]       = acc[mf][nf][1] + b1v;
            Cout[(size_t)(r0 + 8) * N + col]     = acc[mf][nf][2] + b0v;
            Cout[(size_t)(r0 + 8) * N + col + 1] = acc[mf][nf][3] + b1v;
        }
    }
}

// ---------------- RMSNorm + 3D RoPE + split + pack ---------------------------
__device__ __forceinline__ float rope_ang(int p, int token) {
    int t = token >> 9;
    int rem = token & 511;
    int h = rem >> 5, w = rem & 31;
    float pos, expo, d;
    if (p < 22)      { pos = (float)t; expo = (float)(2 * p);        d = 44.f; }
    else if (p < 43) { pos = (float)h; expo = (float)(2 * (p - 22)); d = 42.f; }
    else             { pos = (float)w; expo = (float)(2 * (p - 43)); d = 42.f; }
    return pos * powf(10000.f, -expo / d);
}

__global__ __launch_bounds__(128) void normrope(const float* __restrict__ qnw,
                                                const float* __restrict__ knw) {
    int idx = blockIdx.x * 4 + (threadIdx.x >> 5);
    int lane = threadIdx.x & 31;
    int token = idx >> 4, head = idx & 15;
    int base = token * CDIM + head * HD;
    int e = lane * 4;
    const float SC = 0.08838834764831845f;  // 1/sqrt(128) folded into q

    float ang0 = rope_ang(lane * 2, token);
    float ang1 = rope_ang(lane * 2 + 1, token);
    float co0 = cosf(ang0), si0 = sinf(ang0);
    float co1 = cosf(ang1), si1 = sinf(ang1);
    int ob = (head * NTOK + token) * HD + e;

    {
        float4 q = *reinterpret_cast<const float4*>(&g_qp[base + e]);
        float ss = q.x * q.x + q.y * q.y + q.z * q.z + q.w * q.w;
        #pragma unroll
        for (int o = 16; o; o >>= 1) ss += __shfl_xor_sync(0xffffffffu, ss, o);
        float r = rsqrtf(ss * (1.f / 128.f) + 1e-6f);
        float a0 = q.x * r * qnw[e], a1 = q.y * r * qnw[e + 1];
        float a2 = q.z * r * qnw[e + 2], a3 = q.w * r * qnw[e + 3];
        float o0 = (a0 * co0 - a1 * si0) * SC, o1 = (a0 * si0 + a1 * co0) * SC;
        float o2 = (a2 * co1 - a3 * si1) * SC, o3 = (a2 * si1 + a3 * co1) * SC;
        uint32_t h0, l0, h1, l1;
        splitpack(o0, o1, h0, l0);
        splitpack(o2, o3, h1, l1);
        *reinterpret_cast<uint32_t*>(&g_q_hi[ob])     = h0;
        *reinterpret_cast<uint32_t*>(&g_q_hi[ob + 2]) = h1;
        *reinterpret_cast<uint32_t*>(&g_q_lo[ob])     = l0;
        *reinterpret_cast<uint32_t*>(&g_q_lo[ob + 2]) = l1;
    }
    {
        float4 k = *reinterpret_cast<const float4*>(&g_kp[base + e]);
        float ss = k.x * k.x + k.y * k.y + k.z * k.z + k.w * k.w;
        #pragma unroll
        for (int o = 16; o; o >>= 1) ss += __shfl_xor_sync(0xffffffffu, ss, o);
        float r = rsqrtf(ss * (1.f / 128.f) + 1e-6f);
        float a0 = k.x * r * knw[e], a1 = k.y * r * knw[e + 1];
        float a2 = k.z * r * knw[e + 2], a3 = k.w * r * knw[e + 3];
        float o0 = a0 * co0 - a1 * si0, o1 = a0 * si0 + a1 * co0;
        float o2 = a2 * co1 - a3 * si1, o3 = a2 * si1 + a3 * co1;
        uint32_t h0, l0, h1, l1;
        splitpack(o0, o1, h0, l0);
        splitpack(o2, o3, h1, l1);
        *reinterpret_cast<uint32_t*>(&g_k_hi[ob])     = h0;
        *reinterpret_cast<uint32_t*>(&g_k_hi[ob + 2]) = h1;
        *reinterpret_cast<uint32_t*>(&g_k_lo[ob])     = l0;
        *reinterpret_cast<uint32_t*>(&g_k_lo[ob + 2]) = l1;
    }
    {
        float4 v = *reinterpret_cast<const float4*>(&g_vp[base + e]);
        uint32_t h0, l0, h1, l1;
        splitpack(v.x, v.y, h0, l0);
        splitpack(v.z, v.w, h1, l1);
        *reinterpret_cast<uint32_t*>(&g_v_hi[ob])     = h0;
        *reinterpret_cast<uint32_t*>(&g_v_hi[ob + 2]) = h1;
        *reinterpret_cast<uint32_t*>(&g_v_lo[ob])     = l0;
        *reinterpret_cast<uint32_t*>(&g_v_lo[ob + 2]) = l1;
    }
}

// ---------------- Flash attention (128q tile, 8 warps, 32-key stripes) -------
__global__ __launch_bounds__(256) void attn_kernel() {
    const int head = blockIdx.y;
    const int qb = blockIdx.x * 128;
    const int tid = threadIdx.x, lane = tid & 31, warp = tid >> 5;
    const int g = lane >> 2, cc2 = (lane & 3) * 2;
    const size_t hb = (size_t)head * NTOK * HD;
    const __nv_bfloat16* Qh = g_q_hi + hb;
    const __nv_bfloat16* Ql = g_q_lo + hb;
    const __nv_bfloat16* Kh = g_k_hi + hb;
    const __nv_bfloat16* Kl = g_k_lo + hb;
    const __nv_bfloat16* Vh = g_v_hi + hb;
    const __nv_bfloat16* Vl = g_v_lo + hb;

    __shared__ __nv_bfloat16 sK[2][32][136];
    __shared__ __nv_bfloat16 sVt[2][128][40];

    const int r0 = qb + warp * 16 + g;
    uint32_t qah[8][4], qal[8][4];
    #pragma unroll
    for (int ks = 0; ks < 8; ks++) {
        qah[ks][0] = *reinterpret_cast<const uint32_t*>(&Qh[(size_t)r0 * HD + ks * 16 + cc2]);
        qah[ks][1] = *reinterpret_cast<const uint32_t*>(&Qh[(size_t)(r0 + 8) * HD + ks * 16 + cc2]);
        qah[ks][2] = *reinterpret_cast<const uint32_t*>(&Qh[(size_t)r0 * HD + ks * 16 + cc2 + 8]);
        qah[ks][3] = *reinterpret_cast<const uint32_t*>(&Qh[(size_t)(r0 + 8) * HD + ks * 16 + cc2 + 8]);
        qal[ks][0] = *reinterpret_cast<const uint32_t*>(&Ql[(size_t)r0 * HD + ks * 16 + cc2]);
        qal[ks][1] = *reinterpret_cast<const uint32_t*>(&Ql[(size_t)(r0 + 8) * HD + ks * 16 + cc2]);
        qal[ks][2] = *reinterpret_cast<const uint32_t*>(&Ql[(size_t)r0 * HD + ks * 16 + cc2 + 8]);
        qal[ks][3] = *reinterpret_cast<const uint32_t*>(&Ql[(size_t)(r0 + 8) * HD + ks * 16 + cc2 + 8]);
    }

    float o[16][4] = {};
    float m0v = -1e30f, m1v = -1e30f, l0 = 0.f, l1 = 0.f;

    for (int kt = 0; kt < NTOK / 32; kt++) {
        int kbase = kt * 32;
        #pragma unroll
        for (int i = 0; i < 4; i++) {
            int c = tid + i * 256; int row = c >> 5; int col = (c & 31) * 4;
            size_t ga = (size_t)(kbase + row) * HD + col;
            *reinterpret_cast<uint2*>(&sK[0][row][col]) = *reinterpret_cast<const uint2*>(Kh + ga);
            *reinterpret_cast<uint2*>(&sK[1][row][col]) = *reinterpret_cast<const uint2*>(Kl + ga);
            uint2 vh = *reinterpret_cast<const uint2*>(Vh + ga);
            uint2 vl = *reinterpret_cast<const uint2*>(Vl + ga);
            __nv_bfloat16 th[4]; *reinterpret_cast<uint2*>(th) = vh;
            __nv_bfloat16 tl[4]; *reinterpret_cast<uint2*>(tl) = vl;
            sVt[0][col][row] = th[0]; sVt[0][col + 1][row] = th[1];
            sVt[0][col + 2][row] = th[2]; sVt[0][col + 3][row] = th[3];
            sVt[1][col][row] = tl[0]; sVt[1][col + 1][row] = tl[1];
            sVt[1][col + 2][row] = tl[2]; sVt[1][col + 3][row] = tl[3];
        }
        __syncthreads();

        float s[4][4] = {};
        #pragma unroll
        for (int ks = 0; ks < 8; ks++) {
            #pragma unroll
            for (int nf = 0; nf < 4; nf++) {
                int r = nf * 8 + g;
                uint32_t bh0 = *reinterpret_cast<const uint32_t*>(&sK[0][r][ks * 16 + cc2]);
                uint32_t bh1 = *reinterpret_cast<const uint32_t*>(&sK[0][r][ks * 16 + cc2 + 8]);
                uint32_t bl0 = *reinterpret_cast<const uint32_t*>(&sK[1][r][ks * 16 + cc2]);
                uint32_t bl1 = *reinterpret_cast<const uint32_t*>(&sK[1][r][ks * 16 + cc2 + 8]);
                mma16816(s[nf], qah[ks], bh0, bh1);
                mma16816(s[nf], qah[ks], bl0, bl1);
                mma16816(s[nf], qal[ks], bh0, bh1);
            }
        }

        float mx0 = -1e30f, mx1 = -1e30f;
        #pragma unroll
        for (int nf = 0; nf < 4; nf++) {
            mx0 = fmaxf(mx0, fmaxf(s[nf][0], s[nf][1]));
            mx1 = fmaxf(mx1, fmaxf(s[nf][2], s[nf][3]));
        }
        mx0 = fmaxf(mx0, __shfl_xor_sync(0xffffffffu, mx0, 1));
        mx0 = fmaxf(mx0, __shfl_xor_sync(0xffffffffu, mx0, 2));
        mx1 = fmaxf(mx1, __shfl_xor_sync(0xffffffffu, mx1, 1));
        mx1 = fmaxf(mx1, __shfl_xor_sync(0xffffffffu, mx1, 2));
        float nm0 = fmaxf(m0v, mx0), nm1 = fmaxf(m1v, mx1);
        float c0 = __expf(m0v - nm0), c1 = __expf(m1v - nm1);
        m0v = nm0; m1v = nm1;

        float rs0 = 0.f, rs1 = 0.f;
        #pragma unroll
        for (int nf = 0; nf < 4; nf++) {
            s[nf][0] = __expf(s[nf][0] - nm0); s[nf][1] = __expf(s[nf][1] - nm0);
            s[nf][2] = __expf(s[nf][2] - nm1); s[nf][3] = __expf(s[nf][3] - nm1);
            rs0 += s[nf][0] + s[nf][1];
            rs1 += s[nf][2] + s[nf][3];
        }
        rs0 += __shfl_xor_sync(0xffffffffu, rs0, 1);
        rs0 += __shfl_xor_sync(0xffffffffu, rs0, 2);
        rs1 += __shfl_xor_sync(0xffffffffu, rs1, 1);
        rs1 += __shfl_xor_sync(0xffffffffu, rs1, 2);
        l0 = l0 * c0 + rs0; l1 = l1 * c1 + rs1;
        #pragma unroll
        for (int nf = 0; nf < 16; nf++) {
            o[nf][0] *= c0; o[nf][1] *= c0; o[nf][2] *= c1; o[nf][3] *= c1;
        }

        uint32_t pah[2][4], pal[2][4];
        #pragma unroll
        for (int kk = 0; kk < 2; kk++) {
            splitpack(s[2 * kk][0],     s[2 * kk][1],     pah[kk][0], pal[kk][0]);
            splitpack(s[2 * kk][2],     s[2 * kk][3],     pah[kk][1], pal[kk][1]);
            splitpack(s[2 * kk + 1][0], s[2 * kk + 1][1], pah[kk][2], pal[kk][2]);
            splitpack(s[2 * kk + 1][2], s[2 * kk + 1][3], pah[kk][3], pal[kk][3]);
        }
        #pragma unroll
        for (int kk = 0; kk < 2; kk++) {
            #pragma unroll
            for (int nf = 0; nf < 16; nf++) {
                int d = nf * 8 + g;
                uint32_t bh0 = *reinterpret_cast<const uint32_t*>(&sVt[0][d][kk * 16 + cc2]);
                uint32_t bh1 = *reinterpret_cast<const uint32_t*>(&sVt[0][d][kk * 16 + cc2 + 8]);
                uint32_t bl0 = *reinterpret_cast<const uint32_t*>(&sVt[1][d][kk * 16 + cc2]);
                uint32_t bl1 = *reinterpret_cast<const uint32_t*>(&sVt[1][d][kk * 16 + cc2 + 8]);
                mma16816(o[nf], pah[kk], bh0, bh1);
                mma16816(o[nf], pah[kk], bl0, bl1);
                mma16816(o[nf], pal[kk], bh0, bh1);
            }
        }
        __syncthreads();
    }

    float i0 = 1.f / l0, i1 = 1.f / l1;
    #pragma unroll
    for (int nf = 0; nf < 16; nf++) {
        int col = head * HD + nf * 8 + cc2;
        uint32_t h0, lo0, h1, lo1;
        splitpack(o[nf][0] * i0, o[nf][1] * i0, h0, lo0);
        splitpack(o[nf][2] * i1, o[nf][3] * i1, h1, lo1);
        *reinterpret_cast<uint32_t*>(&g_ao_hi[(size_t)r0 * CDIM + col])       = h0;
        *reinterpret_cast<uint32_t*>(&g_ao_lo[(size_t)r0 * CDIM + col])       = lo0;
        *reinterpret_cast<uint32_t*>(&g_ao_hi[(size_t)(r0 + 8) * CDIM + col]) = h1;
        *reinterpret_cast<uint32_t*>(&g_ao_lo[(size_t)(r0 + 8) * CDIM + col]) = lo1;
    }
}

// ---------------- launch ------------------------------------------------------
extern "C" void kernel_launch(void* const* d_in, const int* in_sizes, int n_in,
                              void* d_out, int out_size) {
    const float* x   = (const float*)d_in[0];
    const float* Wq  = (const float*)d_in[1];
    const float* bq  = (const float*)d_in[2];
    const float* Wk  = (const float*)d_in[3];
    const float* bk  = (const float*)d_in[4];
    const float* Wv  = (const float*)d_in[5];
    const float* bv  = (const float*)d_in[6];
    const float* qnw = (const float*)d_in[7];
    const float* knw = (const float*)d_in[8];
    const float* Wo  = (const float*)d_in[9];
    const float* bo  = (const float*)d_in[10];
    float* out = (float*)d_out;

    const int NW = CDIM * CDIM;
    const int NX = NTOK * CDIM;
    split_bf16<0><<<NX / 1024, 256>>>(x, NX);
    split_bf16<1><<<NW / 1024, 256>>>(Wq, NW);
    split_bf16<2><<<NW / 1024, 256>>>(Wk, NW);
    split_bf16<3><<<NW / 1024, 256>>>(Wv, NW);
    split_bf16<4><<<NW / 1024, 256>>>(Wo, NW);

    dim3 ggrid(CDIM / 128, NTOK / 128);
    gemm_split<0><<<ggrid, 256>>>(bq, nullptr);
    gemm_split<1><<<ggrid, 256>>>(bk, nullptr);
    gemm_split<2><<<ggrid, 256>>>(bv, nullptr);

    normrope<<<NTOK * HEADS / 4, 128>>>(qnw, knw);

    dim3 agrid(NTOK / 128, HEADS);
    attn_kernel<<<agrid, 256>>>();

    gemm_split<3><<<ggrid, 256>>>(bo, out);
}

// round 10
// speedup vs baseline: 1.3025x; 1.0575x over previous
#include <cuda_runtime.h>
#include <cuda_bf16.h>
#include <cstdint>
#include <math.h>

// Problem constants (fixed by setup_inputs: B=1, T=8, H=16, W=32)
#define NTOK 4096
#define CDIM 2048
#define HEADS 16
#define HD 128

// ---------------- scratch (device globals; no allocations allowed) ----------
__device__ __nv_bfloat16 g_x_hi[NTOK * CDIM],  g_x_lo[NTOK * CDIM];
__device__ __nv_bfloat16 g_Wq_hi[CDIM * CDIM], g_Wq_lo[CDIM * CDIM];
__device__ __nv_bfloat16 g_Wk_hi[CDIM * CDIM], g_Wk_lo[CDIM * CDIM];
__device__ __nv_bfloat16 g_Wv_hi[CDIM * CDIM], g_Wv_lo[CDIM * CDIM];
__device__ __nv_bfloat16 g_Wo_hi[CDIM * CDIM], g_Wo_lo[CDIM * CDIM];
__device__ float g_qp[NTOK * CDIM];
__device__ float g_kp[NTOK * CDIM];
__device__ float g_vp[NTOK * CDIM];
__device__ __nv_bfloat16 g_q_hi[NTOK * CDIM], g_q_lo[NTOK * CDIM];
__device__ __nv_bfloat16 g_k_hi[NTOK * CDIM], g_k_lo[NTOK * CDIM];
__device__ __nv_bfloat16 g_v_hi[NTOK * CDIM], g_v_lo[NTOK * CDIM];
__device__ __nv_bfloat16 g_ao_hi[NTOK * CDIM], g_ao_lo[NTOK * CDIM];

// ---------------- helpers ----------------------------------------------------
__device__ __forceinline__ void mma16816(float* c, const uint32_t* a, uint32_t b0, uint32_t b1) {
    asm volatile(
        "mma.sync.aligned.m16n8k16.row.col.f32.bf16.bf16.f32 "
        "{%0,%1,%2,%3}, {%4,%5,%6,%7}, {%8,%9}, {%0,%1,%2,%3};\n"
        : "+f"(c[0]), "+f"(c[1]), "+f"(c[2]), "+f"(c[3])
        : "r"(a[0]), "r"(a[1]), "r"(a[2]), "r"(a[3]), "r"(b0), "r"(b1));
}

__device__ __forceinline__ void split1(float x, __nv_bfloat16& h, __nv_bfloat16& l) {
    h = __float2bfloat16_rn(x);
    l = __float2bfloat16_rn(x - __bfloat162float(h));
}

__device__ __forceinline__ void splitpack(float a, float b, uint32_t& hp, uint32_t& lp) {
    __nv_bfloat16 ha, la, hb, lb;
    split1(a, ha, la);
    split1(b, hb, lb);
    __nv_bfloat162 hh; hh.x = ha; hh.y = hb;
    __nv_bfloat162 ll; ll.x = la; ll.y = lb;
    hp = *reinterpret_cast<uint32_t*>(&hh);
    lp = *reinterpret_cast<uint32_t*>(&ll);
}

__device__ __forceinline__ uint32_t smem_u32(const void* p) {
    uint32_t a;
    asm("{ .reg .u64 t; cvta.to.shared.u64 t, %1; cvt.u32.u64 %0, t; }" : "=r"(a) : "l"(p));
    return a;
}
__device__ __forceinline__ void cpasync16(uint32_t dst, const void* src) {
    asm volatile("cp.async.cg.shared.global [%0], [%1], 16;" :: "r"(dst), "l"(src));
}
__device__ __forceinline__ void cpcommit() {
    asm volatile("cp.async.commit_group;" ::: "memory");
}
template <int N>
__device__ __forceinline__ void cpwait() {
    asm volatile("cp.async.wait_group %0;" :: "n"(N) : "memory");
}

// ---------------- fp32 -> split-bf16 conversion -------------------------------
template <int SEL>
__global__ void split_bf16(const float* __restrict__ src, int n) {
    __nv_bfloat16* hi = (SEL == 0) ? g_x_hi : (SEL == 1) ? g_Wq_hi
                      : (SEL == 2) ? g_Wk_hi : (SEL == 3) ? g_Wv_hi : g_Wo_hi;
    __nv_bfloat16* lo = (SEL == 0) ? g_x_lo : (SEL == 1) ? g_Wq_lo
                      : (SEL == 2) ? g_Wk_lo : (SEL == 3) ? g_Wv_lo : g_Wo_lo;
    int i = (blockIdx.x * blockDim.x + threadIdx.x) * 4;
    if (i < n) {
        float4 v = *reinterpret_cast<const float4*>(src + i);
        uint32_t h0, l0, h1, l1;
        splitpack(v.x, v.y, h0, l0);
        splitpack(v.z, v.w, h1, l1);
        *reinterpret_cast<uint32_t*>(hi + i)     = h0;
        *reinterpret_cast<uint32_t*>(hi + i + 2) = h1;
        *reinterpret_cast<uint32_t*>(lo + i)     = l0;
        *reinterpret_cast<uint32_t*>(lo + i + 2) = l1;
    }
}

// ---------------- split GEMM with cp.async 3-stage pipeline -------------------
// C[m][n] = sum_k A[m][k]*B[n][k] + bias[n]; 3-term split-bf16, fp32 accum.
// CTA 128x128 tile, K step 32, 3 smem stages, one __syncthreads per step.
#define KC 32
#define NST 3
#define TROW 40                          // padded row length (bf16)
#define TILEPAD (128 * TROW * 2)         // 10240 B per tile
#define STAGEB (4 * TILEPAD)             // Ah, Al, Bh, Bl
#define GSMEM (NST * STAGEB)             // 122880 B

template <int SEL>
__global__ __launch_bounds__(256) void gemm_simt(const float* __restrict__ bias,
                                                 float* __restrict__ outp)
{
    const __nv_bfloat16* __restrict__ Ah = (SEL == 3) ? g_ao_hi : g_x_hi;
    const __nv_bfloat16* __restrict__ Al = (SEL == 3) ? g_ao_lo : g_x_lo;
    const __nv_bfloat16* __restrict__ Bh = (SEL == 0) ? g_Wq_hi : (SEL == 1) ? g_Wk_hi
                                         : (SEL == 2) ? g_Wv_hi : g_Wo_hi;
    const __nv_bfloat16* __restrict__ Bl = (SEL == 0) ? g_Wq_lo : (SEL == 1) ? g_Wk_lo
                                         : (SEL == 2) ? g_Wv_lo : g_Wo_lo;
    float* __restrict__ Cout = (SEL == 0) ? g_qp : (SEL == 1) ? g_kp
                             : (SEL == 2) ? g_vp : outp;

    extern __shared__ char dsm[];
    const uint32_t sb = smem_u32(dsm);

    const int tid = threadIdx.x, lane = tid & 31, warp = tid >> 5;
    const int wm = warp >> 2, wn = warp & 3;     // 2x4 warp grid, 64x32 warp tile
    const int m0 = blockIdx.y * 128, n0 = blockIdx.x * 128;
    const int g = lane >> 2, cc2 = (lane & 3) * 2;

    // issue one stage of async loads: 4 tiles x 128 rows x 64B = 2048 x 16B chunks
    auto issue = [&](int kt, int s) {
        #pragma unroll
        for (int j = 0; j < 8; j++) {
            int u = tid + j * 256;
            int t = u >> 9;              // tile id 0..3
            int uu = u & 511;
            int row = uu >> 2;
            int c16 = uu & 3;            // 16B unit within 64B row
            const __nv_bfloat16* src = (t == 0) ? Ah : (t == 1) ? Al : (t == 2) ? Bh : Bl;
            int rbase = (t < 2) ? m0 : n0;
            uint32_t dst = sb + s * STAGEB + t * TILEPAD + row * (TROW * 2) + c16 * 16;
            cpasync16(dst, src + (size_t)(rbase + row) * CDIM + kt * KC + c16 * 8);
        }
        cpcommit();
    };

    issue(0, 0);
    issue(1, 1);

    float acc[4][4][4] = {};
    const int NKT = CDIM / KC;   // 64

    for (int kt = 0; kt < NKT; kt++) {
        const int s = kt % NST;
        // group kt must be complete before reading its stage. For kt < NKT-1
        // the most recent group is kt+1, so wait_group 1 suffices; at the last
        // iteration group kt IS the most recent, so we need wait_group 0.
        if (kt == NKT - 1) cpwait<0>(); else cpwait<1>();
        __syncthreads();
        if (kt + 2 < NKT) issue(kt + 2, (kt + 2) % NST);

        const __nv_bfloat16* pAh = (const __nv_bfloat16*)(dsm + s * STAGEB);
        const __nv_bfloat16* pAl = (const __nv_bfloat16*)(dsm + s * STAGEB + TILEPAD);
        const __nv_bfloat16* pBh = (const __nv_bfloat16*)(dsm + s * STAGEB + 2 * TILEPAD);
        const __nv_bfloat16* pBl = (const __nv_bfloat16*)(dsm + s * STAGEB + 3 * TILEPAD);

        #pragma unroll
        for (int ks = 0; ks < 2; ks++) {
            uint32_t ah[4][4], al[4][4];
            #pragma unroll
            for (int mf = 0; mf < 4; mf++) {
                int r = wm * 64 + mf * 16 + g;
                ah[mf][0] = *reinterpret_cast<const uint32_t*>(&pAh[r * TROW + ks * 16 + cc2]);
                ah[mf][1] = *reinterpret_cast<const uint32_t*>(&pAh[(r + 8) * TROW + ks * 16 + cc2]);
                ah[mf][2] = *reinterpret_cast<const uint32_t*>(&pAh[r * TROW + ks * 16 + cc2 + 8]);
                ah[mf][3] = *reinterpret_cast<const uint32_t*>(&pAh[(r + 8) * TROW + ks * 16 + cc2 + 8]);
                al[mf][0] = *reinterpret_cast<const uint32_t*>(&pAl[r * TROW + ks * 16 + cc2]);
                al[mf][1] = *reinterpret_cast<const uint32_t*>(&pAl[(r + 8) * TROW + ks * 16 + cc2]);
                al[mf][2] = *reinterpret_cast<const uint32_t*>(&pAl[r * TROW + ks * 16 + cc2 + 8]);
                al[mf][3] = *reinterpret_cast<const uint32_t*>(&pAl[(r + 8) * TROW + ks * 16 + cc2 + 8]);
            }
            #pragma unroll
            for (int nf = 0; nf < 4; nf++) {
                int r = wn * 32 + nf * 8 + g;
                uint32_t bh0 = *reinterpret_cast<const uint32_t*>(&pBh[r * TROW + ks * 16 + cc2]);
                uint32_t bh1 = *reinterpret_cast<const uint32_t*>(&pBh[r * TROW + ks * 16 + cc2 + 8]);
                uint32_t bl0 = *reinterpret_cast<const uint32_t*>(&pBl[r * TROW + ks * 16 + cc2]);
                uint32_t bl1 = *reinterpret_cast<const uint32_t*>(&pBl[r * TROW + ks * 16 + cc2 + 8]);
                #pragma unroll
                for (int mf = 0; mf < 4; mf++) {
                    mma16816(acc[mf][nf], ah[mf], bh0, bh1);
                    mma16816(acc[mf][nf], ah[mf], bl0, bl1);
                    mma16816(acc[mf][nf], al[mf], bh0, bh1);
                }
            }
        }
    }

    #pragma unroll
    for (int mf = 0; mf < 4; mf++) {
        int r0 = m0 + wm * 64 + mf * 16 + g;
        #pragma unroll
        for (int nf = 0; nf < 4; nf++) {
            int col = n0 + wn * 32 + nf * 8 + cc2;
            float b0v = bias[col], b1v = bias[col + 1];
            Cout[(size_t)r0 * CDIM + col]           = acc[mf][nf][0] + b0v;
            Cout[(size_t)r0 * CDIM + col + 1]       = acc[mf][nf][1] + b1v;
            Cout[(size_t)(r0 + 8) * CDIM + col]     = acc[mf][nf][2] + b0v;
            Cout[(size_t)(r0 + 8) * CDIM + col + 1] = acc[mf][nf][3] + b1v;
        }
    }
}

// ---------------- RMSNorm + 3D RoPE + split + pack ---------------------------
__device__ __forceinline__ float rope_ang(int p, int token) {
    int t = token >> 9;
    int rem = token & 511;
    int h = rem >> 5, w = rem & 31;
    float pos, expo, d;
    if (p < 22)      { pos = (float)t; expo = (float)(2 * p);        d = 44.f; }
    else if (p < 43) { pos = (float)h; expo = (float)(2 * (p - 22)); d = 42.f; }
    else             { pos = (float)w; expo = (float)(2 * (p - 43)); d = 42.f; }
    return pos * powf(10000.f, -expo / d);
}

__global__ __launch_bounds__(128) void normrope(const float* __restrict__ qnw,
                                                const float* __restrict__ knw) {
    int idx = blockIdx.x * 4 + (threadIdx.x >> 5);
    int lane = threadIdx.x & 31;
    int token = idx >> 4, head = idx & 15;
    int base = token * CDIM + head * HD;
    int e = lane * 4;
    const float SC = 0.08838834764831845f;  // 1/sqrt(128) folded into q

    float ang0 = rope_ang(lane * 2, token);
    float ang1 = rope_ang(lane * 2 + 1, token);
    float co0 = cosf(ang0), si0 = sinf(ang0);
    float co1 = cosf(ang1), si1 = sinf(ang1);
    int ob = (head * NTOK + token) * HD + e;

    {
        float4 q = *reinterpret_cast<const float4*>(&g_qp[base + e]);
        float ss = q.x * q.x + q.y * q.y + q.z * q.z + q.w * q.w;
        #pragma unroll
        for (int o = 16; o; o >>= 1) ss += __shfl_xor_sync(0xffffffffu, ss, o);
        float r = rsqrtf(ss * (1.f / 128.f) + 1e-6f);
        float a0 = q.x * r * qnw[e], a1 = q.y * r * qnw[e + 1];
        float a2 = q.z * r * qnw[e + 2], a3 = q.w * r * qnw[e + 3];
        float o0 = (a0 * co0 - a1 * si0) * SC, o1 = (a0 * si0 + a1 * co0) * SC;
        float o2 = (a2 * co1 - a3 * si1) * SC, o3 = (a2 * si1 + a3 * co1) * SC;
        uint32_t h0, l0, h1, l1;
        splitpack(o0, o1, h0, l0);
        splitpack(o2, o3, h1, l1);
        *reinterpret_cast<uint32_t*>(&g_q_hi[ob])     = h0;
        *reinterpret_cast<uint32_t*>(&g_q_hi[ob + 2]) = h1;
        *reinterpret_cast<uint32_t*>(&g_q_lo[ob])     = l0;
        *reinterpret_cast<uint32_t*>(&g_q_lo[ob + 2]) = l1;
    }
    {
        float4 k = *reinterpret_cast<const float4*>(&g_kp[base + e]);
        float ss = k.x * k.x + k.y * k.y + k.z * k.z + k.w * k.w;
        #pragma unroll
        for (int o = 16; o; o >>= 1) ss += __shfl_xor_sync(0xffffffffu, ss, o);
        float r = rsqrtf(ss * (1.f / 128.f) + 1e-6f);
        float a0 = k.x * r * knw[e], a1 = k.y * r * knw[e + 1];
        float a2 = k.z * r * knw[e + 2], a3 = k.w * r * knw[e + 3];
        float o0 = a0 * co0 - a1 * si0, o1 = a0 * si0 + a1 * co0;
        float o2 = a2 * co1 - a3 * si1, o3 = a2 * si1 + a3 * co1;
        uint32_t h0, l0, h1, l1;
        splitpack(o0, o1, h0, l0);
        splitpack(o2, o3, h1, l1);
        *reinterpret_cast<uint32_t*>(&g_k_hi[ob])     = h0;
        *reinterpret_cast<uint32_t*>(&g_k_hi[ob + 2]) = h1;
        *reinterpret_cast<uint32_t*>(&g_k_lo[ob])     = l0;
        *reinterpret_cast<uint32_t*>(&g_k_lo[ob + 2]) = l1;
    }
    {
        float4 v = *reinterpret_cast<const float4*>(&g_vp[base + e]);
        uint32_t h0, l0, h1, l1;
        splitpack(v.x, v.y, h0, l0);
        splitpack(v.z, v.w, h1, l1);
        *reinterpret_cast<uint32_t*>(&g_v_hi[ob])     = h0;
        *reinterpret_cast<uint32_t*>(&g_v_hi[ob + 2]) = h1;
        *reinterpret_cast<uint32_t*>(&g_v_lo[ob])     = l0;
        *reinterpret_cast<uint32_t*>(&g_v_lo[ob + 2]) = l1;
    }
}

// ---------------- Flash attention (128q tile, 8 warps, 32-key stripes) -------
__global__ __launch_bounds__(256) void attn_kernel() {
    const int head = blockIdx.y;
    const int qb = blockIdx.x * 128;
    const int tid = threadIdx.x, lane = tid & 31, warp = tid >> 5;
    const int g = lane >> 2, cc2 = (lane & 3) * 2;
    const size_t hb = (size_t)head * NTOK * HD;
    const __nv_bfloat16* Qh = g_q_hi + hb;
    const __nv_bfloat16* Ql = g_q_lo + hb;
    const __nv_bfloat16* Kh = g_k_hi + hb;
    const __nv_bfloat16* Kl = g_k_lo + hb;
    const __nv_bfloat16* Vh = g_v_hi + hb;
    const __nv_bfloat16* Vl = g_v_lo + hb;

    __shared__ __nv_bfloat16 sK[2][32][136];
    __shared__ __nv_bfloat16 sVt[2][128][40];

    const int r0 = qb + warp * 16 + g;
    uint32_t qah[8][4], qal[8][4];
    #pragma unroll
    for (int ks = 0; ks < 8; ks++) {
        qah[ks][0] = *reinterpret_cast<const uint32_t*>(&Qh[(size_t)r0 * HD + ks * 16 + cc2]);
        qah[ks][1] = *reinterpret_cast<const uint32_t*>(&Qh[(size_t)(r0 + 8) * HD + ks * 16 + cc2]);
        qah[ks][2] = *reinterpret_cast<const uint32_t*>(&Qh[(size_t)r0 * HD + ks * 16 + cc2 + 8]);
        qah[ks][3] = *reinterpret_cast<const uint32_t*>(&Qh[(size_t)(r0 + 8) * HD + ks * 16 + cc2 + 8]);
        qal[ks][0] = *reinterpret_cast<const uint32_t*>(&Ql[(size_t)r0 * HD + ks * 16 + cc2]);
        qal[ks][1] = *reinterpret_cast<const uint32_t*>(&Ql[(size_t)(r0 + 8) * HD + ks * 16 + cc2]);
        qal[ks][2] = *reinterpret_cast<const uint32_t*>(&Ql[(size_t)r0 * HD + ks * 16 + cc2 + 8]);
        qal[ks][3] = *reinterpret_cast<const uint32_t*>(&Ql[(size_t)(r0 + 8) * HD + ks * 16 + cc2 + 8]);
    }

    float o[16][4] = {};
    float m0v = -1e30f, m1v = -1e30f, l0 = 0.f, l1 = 0.f;

    for (int kt = 0; kt < NTOK / 32; kt++) {
        int kbase = kt * 32;
        #pragma unroll
        for (int i = 0; i < 4; i++) {
            int c = tid + i * 256; int row = c >> 5; int col = (c & 31) * 4;
            size_t ga = (size_t)(kbase + row) * HD + col;
            *reinterpret_cast<uint2*>(&sK[0][row][col]) = *reinterpret_cast<const uint2*>(Kh + ga);
            *reinterpret_cast<uint2*>(&sK[1][row][col]) = *reinterpret_cast<const uint2*>(Kl + ga);
            uint2 vh = *reinterpret_cast<const uint2*>(Vh + ga);
            uint2 vl = *reinterpret_cast<const uint2*>(Vl + ga);
            __nv_bfloat16 th[4]; *reinterpret_cast<uint2*>(th) = vh;
            __nv_bfloat16 tl[4]; *reinterpret_cast<uint2*>(tl) = vl;
            sVt[0][col][row] = th[0]; sVt[0][col + 1][row] = th[1];
            sVt[0][col + 2][row] = th[2]; sVt[0][col + 3][row] = th[3];
            sVt[1][col][row] = tl[0]; sVt[1][col + 1][row] = tl[1];
            sVt[1][col + 2][row] = tl[2]; sVt[1][col + 3][row] = tl[3];
        }
        __syncthreads();

        float s[4][4] = {};
        #pragma unroll
        for (int ks = 0; ks < 8; ks++) {
            #pragma unroll
            for (int nf = 0; nf < 4; nf++) {
                int r = nf * 8 + g;
                uint32_t bh0 = *reinterpret_cast<const uint32_t*>(&sK[0][r][ks * 16 + cc2]);
                uint32_t bh1 = *reinterpret_cast<const uint32_t*>(&sK[0][r][ks * 16 + cc2 + 8]);
                uint32_t bl0 = *reinterpret_cast<const uint32_t*>(&sK[1][r][ks * 16 + cc2]);
                uint32_t bl1 = *reinterpret_cast<const uint32_t*>(&sK[1][r][ks * 16 + cc2 + 8]);
                mma16816(s[nf], qah[ks], bh0, bh1);
                mma16816(s[nf], qah[ks], bl0, bl1);
                mma16816(s[nf], qal[ks], bh0, bh1);
            }
        }

        float mx0 = -1e30f, mx1 = -1e30f;
        #pragma unroll
        for (int nf = 0; nf < 4; nf++) {
            mx0 = fmaxf(mx0, fmaxf(s[nf][0], s[nf][1]));
            mx1 = fmaxf(mx1, fmaxf(s[nf][2], s[nf][3]));
        }
        mx0 = fmaxf(mx0, __shfl_xor_sync(0xffffffffu, mx0, 1));
        mx0 = fmaxf(mx0, __shfl_xor_sync(0xffffffffu, mx0, 2));
        mx1 = fmaxf(mx1, __shfl_xor_sync(0xffffffffu, mx1, 1));
        mx1 = fmaxf(mx1, __shfl_xor_sync(0xffffffffu, mx1, 2));
        float nm0 = fmaxf(m0v, mx0), nm1 = fmaxf(m1v, mx1);
        float c0 = __expf(m0v - nm0), c1 = __expf(m1v - nm1);
        m0v = nm0; m1v = nm1;

        float rs0 = 0.f, rs1 = 0.f;
        #pragma unroll
        for (int nf = 0; nf < 4; nf++) {
            s[nf][0] = __expf(s[nf][0] - nm0); s[nf][1] = __expf(s[nf][1] - nm0);
            s[nf][2] = __expf(s[nf][2] - nm1); s[nf][3] = __expf(s[nf][3] - nm1);
            rs0 += s[nf][0] + s[nf][1];
            rs1 += s[nf][2] + s[nf][3];
        }
        rs0 += __shfl_xor_sync(0xffffffffu, rs0, 1);
        rs0 += __shfl_xor_sync(0xffffffffu, rs0, 2);
        rs1 += __shfl_xor_sync(0xffffffffu, rs1, 1);
        rs1 += __shfl_xor_sync(0xffffffffu, rs1, 2);
        l0 = l0 * c0 + rs0; l1 = l1 * c1 + rs1;
        #pragma unroll
        for (int nf = 0; nf < 16; nf++) {
            o[nf][0] *= c0; o[nf][1] *= c0; o[nf][2] *= c1; o[nf][3] *= c1;
        }

        uint32_t pah[2][4], pal[2][4];
        #pragma unroll
        for (int kk = 0; kk < 2; kk++) {
            splitpack(s[2 * kk][0],     s[2 * kk][1],     pah[kk][0], pal[kk][0]);
            splitpack(s[2 * kk][2],     s[2 * kk][3],     pah[kk][1], pal[kk][1]);
            splitpack(s[2 * kk + 1][0], s[2 * kk + 1][1], pah[kk][2], pal[kk][2]);
            splitpack(s[2 * kk + 1][2], s[2 * kk + 1][3], pah[kk][3], pal[kk][3]);
        }
        #pragma unroll
        for (int kk = 0; kk < 2; kk++) {
            #pragma unroll
            for (int nf = 0; nf < 16; nf++) {
                int d = nf * 8 + g;
                uint32_t bh0 = *reinterpret_cast<const uint32_t*>(&sVt[0][d][kk * 16 + cc2]);
                uint32_t bh1 = *reinterpret_cast<const uint32_t*>(&sVt[0][d][kk * 16 + cc2 + 8]);
                uint32_t bl0 = *reinterpret_cast<const uint32_t*>(&sVt[1][d][kk * 16 + cc2]);
                uint32_t bl1 = *reinterpret_cast<const uint32_t*>(&sVt[1][d][kk * 16 + cc2 + 8]);
                mma16816(o[nf], pah[kk], bh0, bh1);
                mma16816(o[nf], pah[kk], bl0, bl1);
                mma16816(o[nf], pal[kk], bh0, bh1);
            }
        }
        __syncthreads();
    }

    float i0 = 1.f / l0, i1 = 1.f / l1;
    #pragma unroll
    for (int nf = 0; nf < 16; nf++) {
        int col = head * HD + nf * 8 + cc2;
        uint32_t h0, lo0, h1, lo1;
        splitpack(o[nf][0] * i0, o[nf][1] * i0, h0, lo0);
        splitpack(o[nf][2] * i1, o[nf][3] * i1, h1, lo1);
        *reinterpret_cast<uint32_t*>(&g_ao_hi[(size_t)r0 * CDIM + col])       = h0;
        *reinterpret_cast<uint32_t*>(&g_ao_lo[(size_t)r0 * CDIM + col])       = lo0;
        *reinterpret_cast<uint32_t*>(&g_ao_hi[(size_t)(r0 + 8) * CDIM + col]) = h1;
        *reinterpret_cast<uint32_t*>(&g_ao_lo[(size_t)(r0 + 8) * CDIM + col]) = lo1;
    }
}

// ---------------- launch ------------------------------------------------------
extern "C" void kernel_launch(void* const* d_in, const int* in_sizes, int n_in,
                              void* d_out, int out_size) {
    const float* x   = (const float*)d_in[0];
    const float* Wq  = (const float*)d_in[1];
    const float* bq  = (const float*)d_in[2];
    const float* Wk  = (const float*)d_in[3];
    const float* bk  = (const float*)d_in[4];
    const float* Wv  = (const float*)d_in[5];
    const float* bv  = (const float*)d_in[6];
    const float* qnw = (const float*)d_in[7];
    const float* knw = (const float*)d_in[8];
    const float* Wo  = (const float*)d_in[9];
    const float* bo  = (const float*)d_in[10];
    float* out = (float*)d_out;

    cudaFuncSetAttribute(gemm_simt<0>, cudaFuncAttributeMaxDynamicSharedMemorySize, GSMEM);
    cudaFuncSetAttribute(gemm_simt<1>, cudaFuncAttributeMaxDynamicSharedMemorySize, GSMEM);
    cudaFuncSetAttribute(gemm_simt<2>, cudaFuncAttributeMaxDynamicSharedMemorySize, GSMEM);
    cudaFuncSetAttribute(gemm_simt<3>, cudaFuncAttributeMaxDynamicSharedMemorySize, GSMEM);

    const int NW = CDIM * CDIM;
    const int NX = NTOK * CDIM;
    split_bf16<0><<<NX / 1024, 256>>>(x, NX);
    split_bf16<1><<<NW / 1024, 256>>>(Wq, NW);
    split_bf16<2><<<NW / 1024, 256>>>(Wk, NW);
    split_bf16<3><<<NW / 1024, 256>>>(Wv, NW);
    split_bf16<4><<<NW / 1024, 256>>>(Wo, NW);

    dim3 ggrid(CDIM / 128, NTOK / 128);
    gemm_simt<0><<<ggrid, 256, GSMEM>>>(bq, nullptr);
    gemm_simt<1><<<ggrid, 256, GSMEM>>>(bk, nullptr);
    gemm_simt<2><<<ggrid, 256, GSMEM>>>(bv, nullptr);

    normrope<<<NTOK * HEADS / 4, 128>>>(qnw, knw);

    dim3 agrid(NTOK / 128, HEADS);
    attn_kernel<<<agrid, 256>>>();

    gemm_simt<3><<<ggrid, 256, GSMEM>>>(bo, out);
}

// round 11
// speedup vs baseline: 1.8192x; 1.3967x over previous
#include <cuda_runtime.h>
#include <cuda_bf16.h>
#include <cuda_fp16.h>
#include <cstdint>
#include <math.h>

// Problem constants (fixed by setup_inputs: B=1, T=8, H=16, W=32)
#define NTOK 4096
#define CDIM 2048
#define HEADS 16
#define HD 128

// ---------------- scratch (device globals; no allocations allowed) ----------
__device__ __nv_bfloat16 g_x_hi[NTOK * CDIM],  g_x_lo[NTOK * CDIM];
__device__ __nv_bfloat16 g_Wq_hi[CDIM * CDIM], g_Wq_lo[CDIM * CDIM];
__device__ __nv_bfloat16 g_Wk_hi[CDIM * CDIM], g_Wk_lo[CDIM * CDIM];
__device__ __nv_bfloat16 g_Wv_hi[CDIM * CDIM], g_Wv_lo[CDIM * CDIM];
__device__ __nv_bfloat16 g_Wo_hi[CDIM * CDIM], g_Wo_lo[CDIM * CDIM];
__device__ float g_qp[NTOK * CDIM];
__device__ float g_kp[NTOK * CDIM];
__device__ float g_vp[NTOK * CDIM];
// head-major fp16 q/k/v for attention (q has 1/sqrt(HD) folded in)
__device__ __half g_qf[NTOK * CDIM];
__device__ __half g_kf[NTOK * CDIM];
__device__ __half g_vf[NTOK * CDIM];
// token-major attention output, split-bf16 (for 3-term O projection)
__device__ __nv_bfloat16 g_ao_hi[NTOK * CDIM], g_ao_lo[NTOK * CDIM];

// ---------------- helpers ----------------------------------------------------
__device__ __forceinline__ void mma16816(float* c, const uint32_t* a, uint32_t b0, uint32_t b1) {
    asm volatile(
        "mma.sync.aligned.m16n8k16.row.col.f32.bf16.bf16.f32 "
        "{%0,%1,%2,%3}, {%4,%5,%6,%7}, {%8,%9}, {%0,%1,%2,%3};\n"
        : "+f"(c[0]), "+f"(c[1]), "+f"(c[2]), "+f"(c[3])
        : "r"(a[0]), "r"(a[1]), "r"(a[2]), "r"(a[3]), "r"(b0), "r"(b1));
}
__device__ __forceinline__ void mma16816h(float* c, const uint32_t* a, uint32_t b0, uint32_t b1) {
    asm volatile(
        "mma.sync.aligned.m16n8k16.row.col.f32.f16.f16.f32 "
        "{%0,%1,%2,%3}, {%4,%5,%6,%7}, {%8,%9}, {%0,%1,%2,%3};\n"
        : "+f"(c[0]), "+f"(c[1]), "+f"(c[2]), "+f"(c[3])
        : "r"(a[0]), "r"(a[1]), "r"(a[2]), "r"(a[3]), "r"(b0), "r"(b1));
}

__device__ __forceinline__ void split1(float x, __nv_bfloat16& h, __nv_bfloat16& l) {
    h = __float2bfloat16_rn(x);
    l = __float2bfloat16_rn(x - __bfloat162float(h));
}

__device__ __forceinline__ void splitpack(float a, float b, uint32_t& hp, uint32_t& lp) {
    __nv_bfloat16 ha, la, hb, lb;
    split1(a, ha, la);
    split1(b, hb, lb);
    __nv_bfloat162 hh; hh.x = ha; hh.y = hb;
    __nv_bfloat162 ll; ll.x = la; ll.y = lb;
    hp = *reinterpret_cast<uint32_t*>(&hh);
    lp = *reinterpret_cast<uint32_t*>(&ll);
}

__device__ __forceinline__ uint32_t packh(float a, float b) {
    __half2 h = __floats2half2_rn(a, b);
    return *reinterpret_cast<uint32_t*>(&h);
}

__device__ __forceinline__ uint32_t smem_u32(const void* p) {
    uint32_t a;
    asm("{ .reg .u64 t; cvta.to.shared.u64 t, %1; cvt.u32.u64 %0, t; }" : "=r"(a) : "l"(p));
    return a;
}
__device__ __forceinline__ void cpasync16(uint32_t dst, const void* src) {
    asm volatile("cp.async.cg.shared.global [%0], [%1], 16;" :: "r"(dst), "l"(src));
}
__device__ __forceinline__ void cpcommit() {
    asm volatile("cp.async.commit_group;" ::: "memory");
}
template <int N>
__device__ __forceinline__ void cpwait() {
    asm volatile("cp.async.wait_group %0;" :: "n"(N) : "memory");
}

// ---------------- fp32 -> split-bf16 conversion (x + weights) -----------------
template <int SEL>
__global__ void split_bf16(const float* __restrict__ src, int n) {
    __nv_bfloat16* hi = (SEL == 0) ? g_x_hi : (SEL == 1) ? g_Wq_hi
                      : (SEL == 2) ? g_Wk_hi : (SEL == 3) ? g_Wv_hi : g_Wo_hi;
    __nv_bfloat16* lo = (SEL == 0) ? g_x_lo : (SEL == 1) ? g_Wq_lo
                      : (SEL == 2) ? g_Wk_lo : (SEL == 3) ? g_Wv_lo : g_Wo_lo;
    int i = (blockIdx.x * blockDim.x + threadIdx.x) * 4;
    if (i < n) {
        float4 v = *reinterpret_cast<const float4*>(src + i);
        uint32_t h0, l0, h1, l1;
        splitpack(v.x, v.y, h0, l0);
        splitpack(v.z, v.w, h1, l1);
        *reinterpret_cast<uint32_t*>(hi + i)     = h0;
        *reinterpret_cast<uint32_t*>(hi + i + 2) = h1;
        *reinterpret_cast<uint32_t*>(lo + i)     = l0;
        *reinterpret_cast<uint32_t*>(lo + i + 2) = l1;
    }
}

// ---------------- split GEMM with cp.async 3-stage pipeline -------------------
#define KC 32
#define NST 3
#define TROW 40
#define TILEPAD (128 * TROW * 2)
#define STAGEB (4 * TILEPAD)
#define GSMEM (NST * STAGEB)

template <int SEL>
__global__ __launch_bounds__(256) void gemm_simt(const float* __restrict__ bias,
                                                 float* __restrict__ outp)
{
    const __nv_bfloat16* __restrict__ Ah = (SEL == 3) ? g_ao_hi : g_x_hi;
    const __nv_bfloat16* __restrict__ Al = (SEL == 3) ? g_ao_lo : g_x_lo;
    const __nv_bfloat16* __restrict__ Bh = (SEL == 0) ? g_Wq_hi : (SEL == 1) ? g_Wk_hi
                                         : (SEL == 2) ? g_Wv_hi : g_Wo_hi;
    const __nv_bfloat16* __restrict__ Bl = (SEL == 0) ? g_Wq_lo : (SEL == 1) ? g_Wk_lo
                                         : (SEL == 2) ? g_Wv_lo : g_Wo_lo;
    float* __restrict__ Cout = (SEL == 0) ? g_qp : (SEL == 1) ? g_kp
                             : (SEL == 2) ? g_vp : outp;

    extern __shared__ char dsm[];
    const uint32_t sb = smem_u32(dsm);

    const int tid = threadIdx.x, lane = tid & 31, warp = tid >> 5;
    const int wm = warp >> 2, wn = warp & 3;
    const int m0 = blockIdx.y * 128, n0 = blockIdx.x * 128;
    const int g = lane >> 2, cc2 = (lane & 3) * 2;

    auto issue = [&](int kt, int s) {
        #pragma unroll
        for (int j = 0; j < 8; j++) {
            int u = tid + j * 256;
            int t = u >> 9;
            int uu = u & 511;
            int row = uu >> 2;
            int c16 = uu & 3;
            const __nv_bfloat16* src = (t == 0) ? Ah : (t == 1) ? Al : (t == 2) ? Bh : Bl;
            int rbase = (t < 2) ? m0 : n0;
            uint32_t dst = sb + s * STAGEB + t * TILEPAD + row * (TROW * 2) + c16 * 16;
            cpasync16(dst, src + (size_t)(rbase + row) * CDIM + kt * KC + c16 * 8);
        }
        cpcommit();
    };

    issue(0, 0);
    issue(1, 1);

    float acc[4][4][4] = {};
    const int NKT = CDIM / KC;

    for (int kt = 0; kt < NKT; kt++) {
        const int s = kt % NST;
        if (kt == NKT - 1) cpwait<0>(); else cpwait<1>();
        __syncthreads();
        if (kt + 2 < NKT) issue(kt + 2, (kt + 2) % NST);

        const __nv_bfloat16* pAh = (const __nv_bfloat16*)(dsm + s * STAGEB);
        const __nv_bfloat16* pAl = (const __nv_bfloat16*)(dsm + s * STAGEB + TILEPAD);
        const __nv_bfloat16* pBh = (const __nv_bfloat16*)(dsm + s * STAGEB + 2 * TILEPAD);
        const __nv_bfloat16* pBl = (const __nv_bfloat16*)(dsm + s * STAGEB + 3 * TILEPAD);

        #pragma unroll
        for (int ks = 0; ks < 2; ks++) {
            uint32_t ah[4][4], al[4][4];
            #pragma unroll
            for (int mf = 0; mf < 4; mf++) {
                int r = wm * 64 + mf * 16 + g;
                ah[mf][0] = *reinterpret_cast<const uint32_t*>(&pAh[r * TROW + ks * 16 + cc2]);
                ah[mf][1] = *reinterpret_cast<const uint32_t*>(&pAh[(r + 8) * TROW + ks * 16 + cc2]);
                ah[mf][2] = *reinterpret_cast<const uint32_t*>(&pAh[r * TROW + ks * 16 + cc2 + 8]);
                ah[mf][3] = *reinterpret_cast<const uint32_t*>(&pAh[(r + 8) * TROW + ks * 16 + cc2 + 8]);
                al[mf][0] = *reinterpret_cast<const uint32_t*>(&pAl[r * TROW + ks * 16 + cc2]);
                al[mf][1] = *reinterpret_cast<const uint32_t*>(&pAl[(r + 8) * TROW + ks * 16 + cc2]);
                al[mf][2] = *reinterpret_cast<const uint32_t*>(&pAl[r * TROW + ks * 16 + cc2 + 8]);
                al[mf][3] = *reinterpret_cast<const uint32_t*>(&pAl[(r + 8) * TROW + ks * 16 + cc2 + 8]);
            }
            #pragma unroll
            for (int nf = 0; nf < 4; nf++) {
                int r = wn * 32 + nf * 8 + g;
                uint32_t bh0 = *reinterpret_cast<const uint32_t*>(&pBh[r * TROW + ks * 16 + cc2]);
                uint32_t bh1 = *reinterpret_cast<const uint32_t*>(&pBh[r * TROW + ks * 16 + cc2 + 8]);
                uint32_t bl0 = *reinterpret_cast<const uint32_t*>(&pBl[r * TROW + ks * 16 + cc2]);
                uint32_t bl1 = *reinterpret_cast<const uint32_t*>(&pBl[r * TROW + ks * 16 + cc2 + 8]);
                #pragma unroll
                for (int mf = 0; mf < 4; mf++) {
                    mma16816(acc[mf][nf], ah[mf], bh0, bh1);
                    mma16816(acc[mf][nf], ah[mf], bl0, bl1);
                    mma16816(acc[mf][nf], al[mf], bh0, bh1);
                }
            }
        }
    }

    #pragma unroll
    for (int mf = 0; mf < 4; mf++) {
        int r0 = m0 + wm * 64 + mf * 16 + g;
        #pragma unroll
        for (int nf = 0; nf < 4; nf++) {
            int col = n0 + wn * 32 + nf * 8 + cc2;
            float b0v = bias[col], b1v = bias[col + 1];
            Cout[(size_t)r0 * CDIM + col]           = acc[mf][nf][0] + b0v;
            Cout[(size_t)r0 * CDIM + col + 1]       = acc[mf][nf][1] + b1v;
            Cout[(size_t)(r0 + 8) * CDIM + col]     = acc[mf][nf][2] + b0v;
            Cout[(size_t)(r0 + 8) * CDIM + col + 1] = acc[mf][nf][3] + b1v;
        }
    }
}

// ---------------- RMSNorm + 3D RoPE + fp16 pack -------------------------------
__device__ __forceinline__ float rope_ang(int p, int token) {
    int t = token >> 9;
    int rem = token & 511;
    int h = rem >> 5, w = rem & 31;
    float pos, expo, d;
    if (p < 22)      { pos = (float)t; expo = (float)(2 * p);        d = 44.f; }
    else if (p < 43) { pos = (float)h; expo = (float)(2 * (p - 22)); d = 42.f; }
    else             { pos = (float)w; expo = (float)(2 * (p - 43)); d = 42.f; }
    return pos * powf(10000.f, -expo / d);
}

__global__ __launch_bounds__(128) void normrope(const float* __restrict__ qnw,
                                                const float* __restrict__ knw) {
    int idx = blockIdx.x * 4 + (threadIdx.x >> 5);
    int lane = threadIdx.x & 31;
    int token = idx >> 4, head = idx & 15;
    int base = token * CDIM + head * HD;
    int e = lane * 4;
    const float SC = 0.08838834764831845f;  // 1/sqrt(128) folded into q

    float ang0 = rope_ang(lane * 2, token);
    float ang1 = rope_ang(lane * 2 + 1, token);
    float co0 = cosf(ang0), si0 = sinf(ang0);
    float co1 = cosf(ang1), si1 = sinf(ang1);
    int ob = (head * NTOK + token) * HD + e;

    {
        float4 q = *reinterpret_cast<const float4*>(&g_qp[base + e]);
        float ss = q.x * q.x + q.y * q.y + q.z * q.z + q.w * q.w;
        #pragma unroll
        for (int o = 16; o; o >>= 1) ss += __shfl_xor_sync(0xffffffffu, ss, o);
        float r = rsqrtf(ss * (1.f / 128.f) + 1e-6f);
        float a0 = q.x * r * qnw[e], a1 = q.y * r * qnw[e + 1];
        float a2 = q.z * r * qnw[e + 2], a3 = q.w * r * qnw[e + 3];
        *reinterpret_cast<__half2*>(&g_qf[ob]) =
            __floats2half2_rn((a0 * co0 - a1 * si0) * SC, (a0 * si0 + a1 * co0) * SC);
        *reinterpret_cast<__half2*>(&g_qf[ob + 2]) =
            __floats2half2_rn((a2 * co1 - a3 * si1) * SC, (a2 * si1 + a3 * co1) * SC);
    }
    {
        float4 k = *reinterpret_cast<const float4*>(&g_kp[base + e]);
        float ss = k.x * k.x + k.y * k.y + k.z * k.z + k.w * k.w;
        #pragma unroll
        for (int o = 16; o; o >>= 1) ss += __shfl_xor_sync(0xffffffffu, ss, o);
        float r = rsqrtf(ss * (1.f / 128.f) + 1e-6f);
        float a0 = k.x * r * knw[e], a1 = k.y * r * knw[e + 1];
        float a2 = k.z * r * knw[e + 2], a3 = k.w * r * knw[e + 3];
        *reinterpret_cast<__half2*>(&g_kf[ob]) =
            __floats2half2_rn(a0 * co0 - a1 * si0, a0 * si0 + a1 * co0);
        *reinterpret_cast<__half2*>(&g_kf[ob + 2]) =
            __floats2half2_rn(a2 * co1 - a3 * si1, a2 * si1 + a3 * co1);
    }
    {
        float4 v = *reinterpret_cast<const float4*>(&g_vp[base + e]);
        *reinterpret_cast<__half2*>(&g_vf[ob])     = __floats2half2_rn(v.x, v.y);
        *reinterpret_cast<__half2*>(&g_vf[ob + 2]) = __floats2half2_rn(v.z, v.w);
    }
}

// ---------------- Flash attention (128q tile, 8 warps, fp16 1-term) ----------
__global__ __launch_bounds__(256) void attn_kernel() {
    const int head = blockIdx.y;
    const int qb = blockIdx.x * 128;
    const int tid = threadIdx.x, lane = tid & 31, warp = tid >> 5;
    const int g = lane >> 2, cc2 = (lane & 3) * 2;
    const size_t hb = (size_t)head * NTOK * HD;
    const __half* Qf = g_qf + hb;
    const __half* Kf = g_kf + hb;
    const __half* Vf = g_vf + hb;

    __shared__ __half sK[32][136];
    __shared__ __half sVt[128][40];

    const int r0 = qb + warp * 16 + g;
    uint32_t qa[8][4];
    #pragma unroll
    for (int ks = 0; ks < 8; ks++) {
        qa[ks][0] = *reinterpret_cast<const uint32_t*>(&Qf[(size_t)r0 * HD + ks * 16 + cc2]);
        qa[ks][1] = *reinterpret_cast<const uint32_t*>(&Qf[(size_t)(r0 + 8) * HD + ks * 16 + cc2]);
        qa[ks][2] = *reinterpret_cast<const uint32_t*>(&Qf[(size_t)r0 * HD + ks * 16 + cc2 + 8]);
        qa[ks][3] = *reinterpret_cast<const uint32_t*>(&Qf[(size_t)(r0 + 8) * HD + ks * 16 + cc2 + 8]);
    }

    float o[16][4] = {};
    float m0v = -1e30f, m1v = -1e30f, l0 = 0.f, l1 = 0.f;

    for (int kt = 0; kt < NTOK / 32; kt++) {
        int kbase = kt * 32;
        #pragma unroll
        for (int i = 0; i < 4; i++) {
            int c = tid + i * 256; int row = c >> 5; int col = (c & 31) * 4;
            size_t ga = (size_t)(kbase + row) * HD + col;
            *reinterpret_cast<uint2*>(&sK[row][col]) = *reinterpret_cast<const uint2*>(Kf + ga);
            uint2 vh = *reinterpret_cast<const uint2*>(Vf + ga);
            __half th[4]; *reinterpret_cast<uint2*>(th) = vh;
            sVt[col][row] = th[0]; sVt[col + 1][row] = th[1];
            sVt[col + 2][row] = th[2]; sVt[col + 3][row] = th[3];
        }
        __syncthreads();

        float s[4][4] = {};
        #pragma unroll
        for (int ks = 0; ks < 8; ks++) {
            #pragma unroll
            for (int nf = 0; nf < 4; nf++) {
                int r = nf * 8 + g;
                uint32_t b0 = *reinterpret_cast<const uint32_t*>(&sK[r][ks * 16 + cc2]);
                uint32_t b1 = *reinterpret_cast<const uint32_t*>(&sK[r][ks * 16 + cc2 + 8]);
                mma16816h(s[nf], qa[ks], b0, b1);
            }
        }

        float mx0 = -1e30f, mx1 = -1e30f;
        #pragma unroll
        for (int nf = 0; nf < 4; nf++) {
            mx0 = fmaxf(mx0, fmaxf(s[nf][0], s[nf][1]));
            mx1 = fmaxf(mx1, fmaxf(s[nf][2], s[nf][3]));
        }
        mx0 = fmaxf(mx0, __shfl_xor_sync(0xffffffffu, mx0, 1));
        mx0 = fmaxf(mx0, __shfl_xor_sync(0xffffffffu, mx0, 2));
        mx1 = fmaxf(mx1, __shfl_xor_sync(0xffffffffu, mx1, 1));
        mx1 = fmaxf(mx1, __shfl_xor_sync(0xffffffffu, mx1, 2));
        float nm0 = fmaxf(m0v, mx0), nm1 = fmaxf(m1v, mx1);
        float c0 = __expf(m0v - nm0), c1 = __expf(m1v - nm1);
        m0v = nm0; m1v = nm1;

        float rs0 = 0.f, rs1 = 0.f;
        #pragma unroll
        for (int nf = 0; nf < 4; nf++) {
            s[nf][0] = __expf(s[nf][0] - nm0); s[nf][1] = __expf(s[nf][1] - nm0);
            s[nf][2] = __expf(s[nf][2] - nm1); s[nf][3] = __expf(s[nf][3] - nm1);
            rs0 += s[nf][0] + s[nf][1];
            rs1 += s[nf][2] + s[nf][3];
        }
        rs0 += __shfl_xor_sync(0xffffffffu, rs0, 1);
        rs0 += __shfl_xor_sync(0xffffffffu, rs0, 2);
        rs1 += __shfl_xor_sync(0xffffffffu, rs1, 1);
        rs1 += __shfl_xor_sync(0xffffffffu, rs1, 2);
        l0 = l0 * c0 + rs0; l1 = l1 * c1 + rs1;
        #pragma unroll
        for (int nf = 0; nf < 16; nf++) {
            o[nf][0] *= c0; o[nf][1] *= c0; o[nf][2] *= c1; o[nf][3] *= c1;
        }

        uint32_t pa[2][4];
        #pragma unroll
        for (int kk = 0; kk < 2; kk++) {
            pa[kk][0] = packh(s[2 * kk][0],     s[2 * kk][1]);
            pa[kk][1] = packh(s[2 * kk][2],     s[2 * kk][3]);
            pa[kk][2] = packh(s[2 * kk + 1][0], s[2 * kk + 1][1]);
            pa[kk][3] = packh(s[2 * kk + 1][2], s[2 * kk + 1][3]);
        }
        #pragma unroll
        for (int kk = 0; kk < 2; kk++) {
            #pragma unroll
            for (int nf = 0; nf < 16; nf++) {
                int d = nf * 8 + g;
                uint32_t b0 = *reinterpret_cast<const uint32_t*>(&sVt[d][kk * 16 + cc2]);
                uint32_t b1 = *reinterpret_cast<const uint32_t*>(&sVt[d][kk * 16 + cc2 + 8]);
                mma16816h(o[nf], pa[kk], b0, b1);
            }
        }
        __syncthreads();
    }

    float i0 = 1.f / l0, i1 = 1.f / l1;
    #pragma unroll
    for (int nf = 0; nf < 16; nf++) {
        int col = head * HD + nf * 8 + cc2;
        uint32_t h0, lo0, h1, lo1;
        splitpack(o[nf][0] * i0, o[nf][1] * i0, h0, lo0);
        splitpack(o[nf][2] * i1, o[nf][3] * i1, h1, lo1);
        *reinterpret_cast<uint32_t*>(&g_ao_hi[(size_t)r0 * CDIM + col])       = h0;
        *reinterpret_cast<uint32_t*>(&g_ao_lo[(size_t)r0 * CDIM + col])       = lo0;
        *reinterpret_cast<uint32_t*>(&g_ao_hi[(size_t)(r0 + 8) * CDIM + col]) = h1;
        *reinterpret_cast<uint32_t*>(&g_ao_lo[(size_t)(r0 + 8) * CDIM + col]) = lo1;
    }
}

// ---------------- launch ------------------------------------------------------
extern "C" void kernel_launch(void* const* d_in, const int* in_sizes, int n_in,
                              void* d_out, int out_size) {
    const float* x   = (const float*)d_in[0];
    const float* Wq  = (const float*)d_in[1];
    const float* bq  = (const float*)d_in[2];
    const float* Wk  = (const float*)d_in[3];
    const float* bk  = (const float*)d_in[4];
    const float* Wv  = (const float*)d_in[5];
    const float* bv  = (const float*)d_in[6];
    const float* qnw = (const float*)d_in[7];
    const float* knw = (const float*)d_in[8];
    const float* Wo  = (const float*)d_in[9];
    const float* bo  = (const float*)d_in[10];
    float* out = (float*)d_out;

    cudaFuncSetAttribute(gemm_simt<0>, cudaFuncAttributeMaxDynamicSharedMemorySize, GSMEM);
    cudaFuncSetAttribute(gemm_simt<1>, cudaFuncAttributeMaxDynamicSharedMemorySize, GSMEM);
    cudaFuncSetAttribute(gemm_simt<2>, cudaFuncAttributeMaxDynamicSharedMemorySize, GSMEM);
    cudaFuncSetAttribute(gemm_simt<3>, cudaFuncAttributeMaxDynamicSharedMemorySize, GSMEM);

    const int NW = CDIM * CDIM;
    const int NX = NTOK * CDIM;
    split_bf16<0><<<NX / 1024, 256>>>(x, NX);
    split_bf16<1><<<NW / 1024, 256>>>(Wq, NW);
    split_bf16<2><<<NW / 1024, 256>>>(Wk, NW);
    split_bf16<3><<<NW / 1024, 256>>>(Wv, NW);
    split_bf16<4><<<NW / 1024, 256>>>(Wo, NW);

    dim3 ggrid(CDIM / 128, NTOK / 128);
    gemm_simt<0><<<ggrid, 256, GSMEM>>>(bq, nullptr);
    gemm_simt<1><<<ggrid, 256, GSMEM>>>(bk, nullptr);
    gemm_simt<2><<<ggrid, 256, GSMEM>>>(bv, nullptr);

    normrope<<<NTOK * HEADS / 4, 128>>>(qnw, knw);

    dim3 agrid(NTOK / 128, HEADS);
    attn_kernel<<<agrid, 256>>>();

    gemm_simt<3><<<ggrid, 256, GSMEM>>>(bo, out);
}

// round 12
// speedup vs baseline: 2.5747x; 1.4153x over previous
#include <cuda_runtime.h>
#include <cuda_bf16.h>
#include <cuda_fp16.h>
#include <cstdint>
#include <math.h>

// Problem constants (fixed by setup_inputs: B=1, T=8, H=16, W=32)
#define NTOK 4096
#define CDIM 2048
#define HEADS 16
#define HD 128

// ---------------- scratch (device globals; no allocations allowed) ----------
__device__ __half g_xf[NTOK * CDIM];
__device__ __half g_Wqf[CDIM * CDIM];
__device__ __half g_Wkf[CDIM * CDIM];
__device__ __half g_Wvf[CDIM * CDIM];
__device__ __half g_Wof[CDIM * CDIM];
__device__ float g_qp[NTOK * CDIM];
__device__ float g_kp[NTOK * CDIM];
__device__ float g_vp[NTOK * CDIM];
// head-major fp16 q/k/v for attention (q has 1/sqrt(HD) folded in)
__device__ __half g_qf[NTOK * CDIM];
__device__ __half g_kf[NTOK * CDIM];
__device__ __half g_vf[NTOK * CDIM];
// token-major fp16 attention output
__device__ __half g_aof[NTOK * CDIM];

// ---------------- helpers ----------------------------------------------------
__device__ __forceinline__ void mma16816h(float* c, const uint32_t* a, uint32_t b0, uint32_t b1) {
    asm volatile(
        "mma.sync.aligned.m16n8k16.row.col.f32.f16.f16.f32 "
        "{%0,%1,%2,%3}, {%4,%5,%6,%7}, {%8,%9}, {%0,%1,%2,%3};\n"
        : "+f"(c[0]), "+f"(c[1]), "+f"(c[2]), "+f"(c[3])
        : "r"(a[0]), "r"(a[1]), "r"(a[2]), "r"(a[3]), "r"(b0), "r"(b1));
}

__device__ __forceinline__ uint32_t packh(float a, float b) {
    __half2 h = __floats2half2_rn(a, b);
    return *reinterpret_cast<uint32_t*>(&h);
}

__device__ __forceinline__ uint32_t smem_u32(const void* p) {
    uint32_t a;
    asm("{ .reg .u64 t; cvta.to.shared.u64 t, %1; cvt.u32.u64 %0, t; }" : "=r"(a) : "l"(p));
    return a;
}
__device__ __forceinline__ void cpasync16(uint32_t dst, const void* src) {
    asm volatile("cp.async.cg.shared.global [%0], [%1], 16;" :: "r"(dst), "l"(src));
}
__device__ __forceinline__ void cpcommit() {
    asm volatile("cp.async.commit_group;" ::: "memory");
}
template <int N>
__device__ __forceinline__ void cpwait() {
    asm volatile("cp.async.wait_group %0;" :: "n"(N) : "memory");
}

// ---------------- fp32 -> fp16 conversion -------------------------------------
template <int SEL>
__global__ void cvt_f16(const float* __restrict__ src, int n) {
    __half* dst = (SEL == 0) ? g_xf : (SEL == 1) ? g_Wqf
                : (SEL == 2) ? g_Wkf : (SEL == 3) ? g_Wvf : g_Wof;
    int i = (blockIdx.x * blockDim.x + threadIdx.x) * 4;
    if (i < n) {
        float4 v = *reinterpret_cast<const float4*>(src + i);
        *reinterpret_cast<__half2*>(dst + i)     = __floats2half2_rn(v.x, v.y);
        *reinterpret_cast<__half2*>(dst + i + 2) = __floats2half2_rn(v.z, v.w);
    }
}

// ---------------- fp16 GEMM with cp.async 3-stage pipeline --------------------
// C[m][n] = sum_k A[m][k]*B[n][k] + bias[n]; fp16 operands, fp32 accum.
// CTA 128x128 tile, K step 32, 3 smem stages, one __syncthreads per step.
#define KC 32
#define NST 3
#define TROW 40                          // padded row length (halves)
#define TILEPAD (128 * TROW * 2)         // 10240 B per tile
#define STAGEB (2 * TILEPAD)             // A, B
#define GSMEM (NST * STAGEB)             // 61440 B

template <int SEL>
__global__ __launch_bounds__(256) void gemm_f16(const float* __restrict__ bias,
                                                float* __restrict__ outp)
{
    const __half* __restrict__ A = (SEL == 3) ? g_aof : g_xf;
    const __half* __restrict__ B = (SEL == 0) ? g_Wqf : (SEL == 1) ? g_Wkf
                                 : (SEL == 2) ? g_Wvf : g_Wof;
    float* __restrict__ Cout = (SEL == 0) ? g_qp : (SEL == 1) ? g_kp
                             : (SEL == 2) ? g_vp : outp;

    extern __shared__ char dsm[];
    const uint32_t sb = smem_u32(dsm);

    const int tid = threadIdx.x, lane = tid & 31, warp = tid >> 5;
    const int wm = warp >> 2, wn = warp & 3;     // 2x4 warp grid, 64x32 warp tile
    const int m0 = blockIdx.y * 128, n0 = blockIdx.x * 128;
    const int g = lane >> 2, cc2 = (lane & 3) * 2;

    // issue one stage: 2 tiles x 128 rows x 64B = 1024 x 16B chunks
    auto issue = [&](int kt, int s) {
        #pragma unroll
        for (int j = 0; j < 4; j++) {
            int u = tid + j * 256;
            int t = u >> 9;              // tile id 0..1
            int uu = u & 511;
            int row = uu >> 2;
            int c16 = uu & 3;            // 16B unit within 64B row
            const __half* src = (t == 0) ? A : B;
            int rbase = (t == 0) ? m0 : n0;
            uint32_t dst = sb + s * STAGEB + t * TILEPAD + row * (TROW * 2) + c16 * 16;
            cpasync16(dst, src + (size_t)(rbase + row) * CDIM + kt * KC + c16 * 8);
        }
        cpcommit();
    };

    issue(0, 0);
    issue(1, 1);

    float acc[4][4][4] = {};
    const int NKT = CDIM / KC;   // 64

    for (int kt = 0; kt < NKT; kt++) {
        const int s = kt % NST;
        if (kt == NKT - 1) cpwait<0>(); else cpwait<1>();
        __syncthreads();
        if (kt + 2 < NKT) issue(kt + 2, (kt + 2) % NST);

        const __half* pA = (const __half*)(dsm + s * STAGEB);
        const __half* pB = (const __half*)(dsm + s * STAGEB + TILEPAD);

        #pragma unroll
        for (int ks = 0; ks < 2; ks++) {
            uint32_t a[4][4];
            #pragma unroll
            for (int mf = 0; mf < 4; mf++) {
                int r = wm * 64 + mf * 16 + g;
                a[mf][0] = *reinterpret_cast<const uint32_t*>(&pA[r * TROW + ks * 16 + cc2]);
                a[mf][1] = *reinterpret_cast<const uint32_t*>(&pA[(r + 8) * TROW + ks * 16 + cc2]);
                a[mf][2] = *reinterpret_cast<const uint32_t*>(&pA[r * TROW + ks * 16 + cc2 + 8]);
                a[mf][3] = *reinterpret_cast<const uint32_t*>(&pA[(r + 8) * TROW + ks * 16 + cc2 + 8]);
            }
            #pragma unroll
            for (int nf = 0; nf < 4; nf++) {
                int r = wn * 32 + nf * 8 + g;
                uint32_t b0 = *reinterpret_cast<const uint32_t*>(&pB[r * TROW + ks * 16 + cc2]);
                uint32_t b1 = *reinterpret_cast<const uint32_t*>(&pB[r * TROW + ks * 16 + cc2 + 8]);
                #pragma unroll
                for (int mf = 0; mf < 4; mf++) {
                    mma16816h(acc[mf][nf], a[mf], b0, b1);
                }
            }
        }
    }

    #pragma unroll
    for (int mf = 0; mf < 4; mf++) {
        int r0 = m0 + wm * 64 + mf * 16 + g;
        #pragma unroll
        for (int nf = 0; nf < 4; nf++) {
            int col = n0 + wn * 32 + nf * 8 + cc2;
            float b0v = bias[col], b1v = bias[col + 1];
            Cout[(size_t)r0 * CDIM + col]           = acc[mf][nf][0] + b0v;
            Cout[(size_t)r0 * CDIM + col + 1]       = acc[mf][nf][1] + b1v;
            Cout[(size_t)(r0 + 8) * CDIM + col]     = acc[mf][nf][2] + b0v;
            Cout[(size_t)(r0 + 8) * CDIM + col + 1] = acc[mf][nf][3] + b1v;
        }
    }
}

// ---------------- RMSNorm + 3D RoPE + fp16 pack -------------------------------
__device__ __forceinline__ float rope_ang(int p, int token) {
    int t = token >> 9;
    int rem = token & 511;
    int h = rem >> 5, w = rem & 31;
    float pos, expo, d;
    if (p < 22)      { pos = (float)t; expo = (float)(2 * p);        d = 44.f; }
    else if (p < 43) { pos = (float)h; expo = (float)(2 * (p - 22)); d = 42.f; }
    else             { pos = (float)w; expo = (float)(2 * (p - 43)); d = 42.f; }
    return pos * powf(10000.f, -expo / d);
}

__global__ __launch_bounds__(128) void normrope(const float* __restrict__ qnw,
                                                const float* __restrict__ knw) {
    int idx = blockIdx.x * 4 + (threadIdx.x >> 5);
    int lane = threadIdx.x & 31;
    int token = idx >> 4, head = idx & 15;
    int base = token * CDIM + head * HD;
    int e = lane * 4;
    const float SC = 0.08838834764831845f;  // 1/sqrt(128) folded into q

    float ang0 = rope_ang(lane * 2, token);
    float ang1 = rope_ang(lane * 2 + 1, token);
    float co0 = cosf(ang0), si0 = sinf(ang0);
    float co1 = cosf(ang1), si1 = sinf(ang1);
    int ob = (head * NTOK + token) * HD + e;

    {
        float4 q = *reinterpret_cast<const float4*>(&g_qp[base + e]);
        float ss = q.x * q.x + q.y * q.y + q.z * q.z + q.w * q.w;
        #pragma unroll
        for (int o = 16; o; o >>= 1) ss += __shfl_xor_sync(0xffffffffu, ss, o);
        float r = rsqrtf(ss * (1.f / 128.f) + 1e-6f);
        float a0 = q.x * r * qnw[e], a1 = q.y * r * qnw[e + 1];
        float a2 = q.z * r * qnw[e + 2], a3 = q.w * r * qnw[e + 3];
        *reinterpret_cast<__half2*>(&g_qf[ob]) =
            __floats2half2_rn((a0 * co0 - a1 * si0) * SC, (a0 * si0 + a1 * co0) * SC);
        *reinterpret_cast<__half2*>(&g_qf[ob + 2]) =
            __floats2half2_rn((a2 * co1 - a3 * si1) * SC, (a2 * si1 + a3 * co1) * SC);
    }
    {
        float4 k = *reinterpret_cast<const float4*>(&g_kp[base + e]);
        float ss = k.x * k.x + k.y * k.y + k.z * k.z + k.w * k.w;
        #pragma unroll
        for (int o = 16; o; o >>= 1) ss += __shfl_xor_sync(0xffffffffu, ss, o);
        float r = rsqrtf(ss * (1.f / 128.f) + 1e-6f);
        float a0 = k.x * r * knw[e], a1 = k.y * r * knw[e + 1];
        float a2 = k.z * r * knw[e + 2], a3 = k.w * r * knw[e + 3];
        *reinterpret_cast<__half2*>(&g_kf[ob]) =
            __floats2half2_rn(a0 * co0 - a1 * si0, a0 * si0 + a1 * co0);
        *reinterpret_cast<__half2*>(&g_kf[ob + 2]) =
            __floats2half2_rn(a2 * co1 - a3 * si1, a2 * si1 + a3 * co1);
    }
    {
        float4 v = *reinterpret_cast<const float4*>(&g_vp[base + e]);
        *reinterpret_cast<__half2*>(&g_vf[ob])     = __floats2half2_rn(v.x, v.y);
        *reinterpret_cast<__half2*>(&g_vf[ob + 2]) = __floats2half2_rn(v.z, v.w);
    }
}

// ---------------- Flash attention (128q tile, 8 warps, fp16 1-term) ----------
__global__ __launch_bounds__(256) void attn_kernel() {
    const int head = blockIdx.y;
    const int qb = blockIdx.x * 128;
    const int tid = threadIdx.x, lane = tid & 31, warp = tid >> 5;
    const int g = lane >> 2, cc2 = (lane & 3) * 2;
    const size_t hb = (size_t)head * NTOK * HD;
    const __half* Qf = g_qf + hb;
    const __half* Kf = g_kf + hb;
    const __half* Vf = g_vf + hb;

    __shared__ __half sK[32][136];
    __shared__ __half sVt[128][40];

    const int r0 = qb + warp * 16 + g;
    uint32_t qa[8][4];
    #pragma unroll
    for (int ks = 0; ks < 8; ks++) {
        qa[ks][0] = *reinterpret_cast<const uint32_t*>(&Qf[(size_t)r0 * HD + ks * 16 + cc2]);
        qa[ks][1] = *reinterpret_cast<const uint32_t*>(&Qf[(size_t)(r0 + 8) * HD + ks * 16 + cc2]);
        qa[ks][2] = *reinterpret_cast<const uint32_t*>(&Qf[(size_t)r0 * HD + ks * 16 + cc2 + 8]);
        qa[ks][3] = *reinterpret_cast<const uint32_t*>(&Qf[(size_t)(r0 + 8) * HD + ks * 16 + cc2 + 8]);
    }

    float o[16][4] = {};
    float m0v = -1e30f, m1v = -1e30f, l0 = 0.f, l1 = 0.f;

    for (int kt = 0; kt < NTOK / 32; kt++) {
        int kbase = kt * 32;
        #pragma unroll
        for (int i = 0; i < 4; i++) {
            int c = tid + i * 256; int row = c >> 5; int col = (c & 31) * 4;
            size_t ga = (size_t)(kbase + row) * HD + col;
            *reinterpret_cast<uint2*>(&sK[row][col]) = *reinterpret_cast<const uint2*>(Kf + ga);
            uint2 vh = *reinterpret_cast<const uint2*>(Vf + ga);
            __half th[4]; *reinterpret_cast<uint2*>(th) = vh;
            sVt[col][row] = th[0]; sVt[col + 1][row] = th[1];
            sVt[col + 2][row] = th[2]; sVt[col + 3][row] = th[3];
        }
        __syncthreads();

        float s[4][4] = {};
        #pragma unroll
        for (int ks = 0; ks < 8; ks++) {
            #pragma unroll
            for (int nf = 0; nf < 4; nf++) {
                int r = nf * 8 + g;
                uint32_t b0 = *reinterpret_cast<const uint32_t*>(&sK[r][ks * 16 + cc2]);
                uint32_t b1 = *reinterpret_cast<const uint32_t*>(&sK[r][ks * 16 + cc2 + 8]);
                mma16816h(s[nf], qa[ks], b0, b1);
            }
        }

        float mx0 = -1e30f, mx1 = -1e30f;
        #pragma unroll
        for (int nf = 0; nf < 4; nf++) {
            mx0 = fmaxf(mx0, fmaxf(s[nf][0], s[nf][1]));
            mx1 = fmaxf(mx1, fmaxf(s[nf][2], s[nf][3]));
        }
        mx0 = fmaxf(mx0, __shfl_xor_sync(0xffffffffu, mx0, 1));
        mx0 = fmaxf(mx0, __shfl_xor_sync(0xffffffffu, mx0, 2));
        mx1 = fmaxf(mx1, __shfl_xor_sync(0xffffffffu, mx1, 1));
        mx1 = fmaxf(mx1, __shfl_xor_sync(0xffffffffu, mx1, 2));
        float nm0 = fmaxf(m0v, mx0), nm1 = fmaxf(m1v, mx1);
        float c0 = __expf(m0v - nm0), c1 = __expf(m1v - nm1);
        m0v = nm0; m1v = nm1;

        float rs0 = 0.f, rs1 = 0.f;
        #pragma unroll
        for (int nf = 0; nf < 4; nf++) {
            s[nf][0] = __expf(s[nf][0] - nm0); s[nf][1] = __expf(s[nf][1] - nm0);
            s[nf][2] = __expf(s[nf][2] - nm1); s[nf][3] = __expf(s[nf][3] - nm1);
            rs0 += s[nf][0] + s[nf][1];
            rs1 += s[nf][2] + s[nf][3];
        }
        rs0 += __shfl_xor_sync(0xffffffffu, rs0, 1);
        rs0 += __shfl_xor_sync(0xffffffffu, rs0, 2);
        rs1 += __shfl_xor_sync(0xffffffffu, rs1, 1);
        rs1 += __shfl_xor_sync(0xffffffffu, rs1, 2);
        l0 = l0 * c0 + rs0; l1 = l1 * c1 + rs1;
        #pragma unroll
        for (int nf = 0; nf < 16; nf++) {
            o[nf][0] *= c0; o[nf][1] *= c0; o[nf][2] *= c1; o[nf][3] *= c1;
        }

        uint32_t pa[2][4];
        #pragma unroll
        for (int kk = 0; kk < 2; kk++) {
            pa[kk][0] = packh(s[2 * kk][0],     s[2 * kk][1]);
            pa[kk][1] = packh(s[2 * kk][2],     s[2 * kk][3]);
            pa[kk][2] = packh(s[2 * kk + 1][0], s[2 * kk + 1][1]);
            pa[kk][3] = packh(s[2 * kk + 1][2], s[2 * kk + 1][3]);
        }
        #pragma unroll
        for (int kk = 0; kk < 2; kk++) {
            #pragma unroll
            for (int nf = 0; nf < 16; nf++) {
                int d = nf * 8 + g;
                uint32_t b0 = *reinterpret_cast<const uint32_t*>(&sVt[d][kk * 16 + cc2]);
                uint32_t b1 = *reinterpret_cast<const uint32_t*>(&sVt[d][kk * 16 + cc2 + 8]);
                mma16816h(o[nf], pa[kk], b0, b1);
            }
        }
        __syncthreads();
    }

    float i0 = 1.f / l0, i1 = 1.f / l1;
    #pragma unroll
    for (int nf = 0; nf < 16; nf++) {
        int col = head * HD + nf * 8 + cc2;
        *reinterpret_cast<uint32_t*>(&g_aof[(size_t)r0 * CDIM + col]) =
            packh(o[nf][0] * i0, o[nf][1] * i0);
        *reinterpret_cast<uint32_t*>(&g_aof[(size_t)(r0 + 8) * CDIM + col]) =
            packh(o[nf][2] * i1, o[nf][3] * i1);
    }
}

// ---------------- launch ------------------------------------------------------
extern "C" void kernel_launch(void* const* d_in, const int* in_sizes, int n_in,
                              void* d_out, int out_size) {
    const float* x   = (const float*)d_in[0];
    const float* Wq  = (const float*)d_in[1];
    const float* bq  = (const float*)d_in[2];
    const float* Wk  = (const float*)d_in[3];
    const float* bk  = (const float*)d_in[4];
    const float* Wv  = (const float*)d_in[5];
    const float* bv  = (const float*)d_in[6];
    const float* qnw = (const float*)d_in[7];
    const float* knw = (const float*)d_in[8];
    const float* Wo  = (const float*)d_in[9];
    const float* bo  = (const float*)d_in[10];
    float* out = (float*)d_out;

    cudaFuncSetAttribute(gemm_f16<0>, cudaFuncAttributeMaxDynamicSharedMemorySize, GSMEM);
    cudaFuncSetAttribute(gemm_f16<1>, cudaFuncAttributeMaxDynamicSharedMemorySize, GSMEM);
    cudaFuncSetAttribute(gemm_f16<2>, cudaFuncAttributeMaxDynamicSharedMemorySize, GSMEM);
    cudaFuncSetAttribute(gemm_f16<3>, cudaFuncAttributeMaxDynamicSharedMemorySize, GSMEM);

    const int NW = CDIM * CDIM;
    const int NX = NTOK * CDIM;
    cvt_f16<0><<<NX / 1024, 256>>>(x, NX);
    cvt_f16<1><<<NW / 1024, 256>>>(Wq, NW);
    cvt_f16<2><<<NW / 1024, 256>>>(Wk, NW);
    cvt_f16<3><<<NW / 1024, 256>>>(Wv, NW);
    cvt_f16<4><<<NW / 1024, 256>>>(Wo, NW);

    dim3 ggrid(CDIM / 128, NTOK / 128);
    gemm_f16<0><<<ggrid, 256, GSMEM>>>(bq, nullptr);
    gemm_f16<1><<<ggrid, 256, GSMEM>>>(bk, nullptr);
    gemm_f16<2><<<ggrid, 256, GSMEM>>>(bv, nullptr);

    normrope<<<NTOK * HEADS / 4, 128>>>(qnw, knw);

    dim3 agrid(NTOK / 128, HEADS);
    attn_kernel<<<agrid, 256>>>();

    gemm_f16<3><<<ggrid, 256, GSMEM>>>(bo, out);
}

// round 13
// speedup vs baseline: 3.8051x; 1.4779x over previous
#include <cuda_runtime.h>
#include <cuda_bf16.h>
#include <cuda_fp16.h>
#include <cstdint>
#include <math.h>

// Problem constants (fixed by setup_inputs: B=1, T=8, H=16, W=32)
#define NTOK 4096
#define CDIM 2048
#define HEADS 16
#define HD 128

// ---------------- scratch (device globals; no allocations allowed) ----------
__device__ __half g_xf[NTOK * CDIM];
__device__ __half g_Wqf[CDIM * CDIM];
__device__ __half g_Wkf[CDIM * CDIM];
__device__ __half g_Wvf[CDIM * CDIM];
__device__ __half g_Wof[CDIM * CDIM];
__device__ float g_qp[NTOK * CDIM];
__device__ float g_kp[NTOK * CDIM];
__device__ float g_vp[NTOK * CDIM];
// head-major fp16 q/k/v for attention (q has 1/sqrt(HD) folded in)
__device__ __half g_qf[NTOK * CDIM];
__device__ __half g_kf[NTOK * CDIM];
__device__ __half g_vf[NTOK * CDIM];
// token-major fp16 attention output
__device__ __half g_aof[NTOK * CDIM];

// ---------------- helpers ----------------------------------------------------
__device__ __forceinline__ void mma16816h(float* c, const uint32_t* a, uint32_t b0, uint32_t b1) {
    asm volatile(
        "mma.sync.aligned.m16n8k16.row.col.f32.f16.f16.f32 "
        "{%0,%1,%2,%3}, {%4,%5,%6,%7}, {%8,%9}, {%0,%1,%2,%3};\n"
        : "+f"(c[0]), "+f"(c[1]), "+f"(c[2]), "+f"(c[3])
        : "r"(a[0]), "r"(a[1]), "r"(a[2]), "r"(a[3]), "r"(b0), "r"(b1));
}

__device__ __forceinline__ void ldsm4(uint32_t& r0, uint32_t& r1, uint32_t& r2, uint32_t& r3,
                                      uint32_t addr) {
    asm volatile("ldmatrix.sync.aligned.m8n8.x4.shared.b16 {%0,%1,%2,%3}, [%4];"
                 : "=r"(r0), "=r"(r1), "=r"(r2), "=r"(r3) : "r"(addr));
}
__device__ __forceinline__ void ldsm4t(uint32_t& r0, uint32_t& r1, uint32_t& r2, uint32_t& r3,
                                       uint32_t addr) {
    asm volatile("ldmatrix.sync.aligned.m8n8.x4.trans.shared.b16 {%0,%1,%2,%3}, [%4];"
                 : "=r"(r0), "=r"(r1), "=r"(r2), "=r"(r3) : "r"(addr));
}

__device__ __forceinline__ uint32_t packh(float a, float b) {
    __half2 h = __floats2half2_rn(a, b);
    return *reinterpret_cast<uint32_t*>(&h);
}

__device__ __forceinline__ uint32_t smem_u32(const void* p) {
    uint32_t a;
    asm("{ .reg .u64 t; cvta.to.shared.u64 t, %1; cvt.u32.u64 %0, t; }" : "=r"(a) : "l"(p));
    return a;
}
__device__ __forceinline__ void cpasync16(uint32_t dst, const void* src) {
    asm volatile("cp.async.cg.shared.global [%0], [%1], 16;" :: "r"(dst), "l"(src));
}
__device__ __forceinline__ void cpcommit() {
    asm volatile("cp.async.commit_group;" ::: "memory");
}
template <int N>
__device__ __forceinline__ void cpwait() {
    asm volatile("cp.async.wait_group %0;" :: "n"(N) : "memory");
}

// ---------------- fp32 -> fp16 conversion -------------------------------------
template <int SEL>
__global__ void cvt_f16(const float* __restrict__ src, int n) {
    __half* dst = (SEL == 0) ? g_xf : (SEL == 1) ? g_Wqf
                : (SEL == 2) ? g_Wkf : (SEL == 3) ? g_Wvf : g_Wof;
    int i = (blockIdx.x * blockDim.x + threadIdx.x) * 4;
    if (i < n) {
        float4 v = *reinterpret_cast<const float4*>(src + i);
        *reinterpret_cast<__half2*>(dst + i)     = __floats2half2_rn(v.x, v.y);
        *reinterpret_cast<__half2*>(dst + i + 2) = __floats2half2_rn(v.z, v.w);
    }
}

// ---------------- fp16 GEMM: cp.async 3-stage + ldmatrix ----------------------
// C[m][n] = sum_k A[m][k]*B[n][k] + bias[n]; fp16 operands, fp32 accum.
#define KC 32
#define NST 3
#define TROW 40                          // padded row length (halves)
#define TILEPAD (128 * TROW * 2)         // 10240 B per tile
#define STAGEB (2 * TILEPAD)             // A, B
#define GSMEM (NST * STAGEB)             // 61440 B

template <int SEL>
__global__ __launch_bounds__(256) void gemm_f16(const float* __restrict__ bias,
                                                float* __restrict__ outp)
{
    const __half* __restrict__ A = (SEL == 3) ? g_aof : g_xf;
    const __half* __restrict__ B = (SEL == 0) ? g_Wqf : (SEL == 1) ? g_Wkf
                                 : (SEL == 2) ? g_Wvf : g_Wof;
    float* __restrict__ Cout = (SEL == 0) ? g_qp : (SEL == 1) ? g_kp
                             : (SEL == 2) ? g_vp : outp;

    extern __shared__ char dsm[];
    const uint32_t sb = smem_u32(dsm);

    const int tid = threadIdx.x, lane = tid & 31, warp = tid >> 5;
    const int wm = warp >> 2, wn = warp & 3;     // 2x4 warp grid, 64x32 warp tile
    const int m0 = blockIdx.y * 128, n0 = blockIdx.x * 128;
    const int g = lane >> 2, cc2 = (lane & 3) * 2;

    // ldmatrix per-lane row/col offsets
    const int arow = (lane & 7) + ((lane >> 3) & 1) * 8;   // row within 16 (tiles 0/1)
    const int acol8 = (lane >> 4) * 8;                     // k-half (tiles 2/3)
    const int brow = wn * 32 + (lane >> 3) * 8 + (lane & 7);

    auto issue = [&](int kt, int s) {
        #pragma unroll
        for (int j = 0; j < 4; j++) {
            int u = tid + j * 256;
            int t = u >> 9;
            int uu = u & 511;
            int row = uu >> 2;
            int c16 = uu & 3;
            const __half* src = (t == 0) ? A : B;
            int rbase = (t == 0) ? m0 : n0;
            uint32_t dst = sb + s * STAGEB + t * TILEPAD + row * (TROW * 2) + c16 * 16;
            cpasync16(dst, src + (size_t)(rbase + row) * CDIM + kt * KC + c16 * 8);
        }
        cpcommit();
    };

    issue(0, 0);
    issue(1, 1);

    float acc[4][4][4] = {};
    const int NKT = CDIM / KC;   // 64

    for (int kt = 0; kt < NKT; kt++) {
        const int s = kt % NST;
        if (kt == NKT - 1) cpwait<0>(); else cpwait<1>();
        __syncthreads();
        if (kt + 2 < NKT) issue(kt + 2, (kt + 2) % NST);

        const uint32_t aoff = sb + s * STAGEB;
        const uint32_t boff = aoff + TILEPAD;

        #pragma unroll
        for (int ks = 0; ks < 2; ks++) {
            uint32_t b0v[4], b1v[4];
            ldsm4(b0v[0], b0v[1], b0v[2], b0v[3],
                  boff + (uint32_t)(brow * TROW + ks * 16) * 2);
            ldsm4(b1v[0], b1v[1], b1v[2], b1v[3],
                  boff + (uint32_t)(brow * TROW + ks * 16 + 8) * 2);
            #pragma unroll
            for (int mf = 0; mf < 4; mf++) {
                uint32_t a[4];
                ldsm4(a[0], a[1], a[2], a[3],
                      aoff + (uint32_t)((wm * 64 + mf * 16 + arow) * TROW + ks * 16 + acol8) * 2);
                #pragma unroll
                for (int nf = 0; nf < 4; nf++)
                    mma16816h(acc[mf][nf], a, b0v[nf], b1v[nf]);
            }
        }
    }

    #pragma unroll
    for (int mf = 0; mf < 4; mf++) {
        int r0 = m0 + wm * 64 + mf * 16 + g;
        #pragma unroll
        for (int nf = 0; nf < 4; nf++) {
            int col = n0 + wn * 32 + nf * 8 + cc2;
            float b0v = bias[col], b1v = bias[col + 1];
            float2 o0; o0.x = acc[mf][nf][0] + b0v; o0.y = acc[mf][nf][1] + b1v;
            float2 o1; o1.x = acc[mf][nf][2] + b0v; o1.y = acc[mf][nf][3] + b1v;
            *reinterpret_cast<float2*>(Cout + (size_t)r0 * CDIM + col)       = o0;
            *reinterpret_cast<float2*>(Cout + (size_t)(r0 + 8) * CDIM + col) = o1;
        }
    }
}

// ---------------- RMSNorm + 3D RoPE + fp16 pack -------------------------------
__device__ __forceinline__ float rope_ang(int p, int token) {
    int t = token >> 9;
    int rem = token & 511;
    int h = rem >> 5, w = rem & 31;
    float pos, expo, d;
    if (p < 22)      { pos = (float)t; expo = (float)(2 * p);        d = 44.f; }
    else if (p < 43) { pos = (float)h; expo = (float)(2 * (p - 22)); d = 42.f; }
    else             { pos = (float)w; expo = (float)(2 * (p - 43)); d = 42.f; }
    return pos * powf(10000.f, -expo / d);
}

__global__ __launch_bounds__(128) void normrope(const float* __restrict__ qnw,
                                                const float* __restrict__ knw) {
    int idx = blockIdx.x * 4 + (threadIdx.x >> 5);
    int lane = threadIdx.x & 31;
    int token = idx >> 4, head = idx & 15;
    int base = token * CDIM + head * HD;
    int e = lane * 4;
    const float SC = 0.08838834764831845f;  // 1/sqrt(128) folded into q

    float ang0 = rope_ang(lane * 2, token);
    float ang1 = rope_ang(lane * 2 + 1, token);
    float co0 = cosf(ang0), si0 = sinf(ang0);
    float co1 = cosf(ang1), si1 = sinf(ang1);
    int ob = (head * NTOK + token) * HD + e;

    {
        float4 q = *reinterpret_cast<const float4*>(&g_qp[base + e]);
        float ss = q.x * q.x + q.y * q.y + q.z * q.z + q.w * q.w;
        #pragma unroll
        for (int o = 16; o; o >>= 1) ss += __shfl_xor_sync(0xffffffffu, ss, o);
        float r = rsqrtf(ss * (1.f / 128.f) + 1e-6f);
        float a0 = q.x * r * qnw[e], a1 = q.y * r * qnw[e + 1];
        float a2 = q.z * r * qnw[e + 2], a3 = q.w * r * qnw[e + 3];
        *reinterpret_cast<__half2*>(&g_qf[ob]) =
            __floats2half2_rn((a0 * co0 - a1 * si0) * SC, (a0 * si0 + a1 * co0) * SC);
        *reinterpret_cast<__half2*>(&g_qf[ob + 2]) =
            __floats2half2_rn((a2 * co1 - a3 * si1) * SC, (a2 * si1 + a3 * co1) * SC);
    }
    {
        float4 k = *reinterpret_cast<const float4*>(&g_kp[base + e]);
        float ss = k.x * k.x + k.y * k.y + k.z * k.z + k.w * k.w;
        #pragma unroll
        for (int o = 16; o; o >>= 1) ss += __shfl_xor_sync(0xffffffffu, ss, o);
        float r = rsqrtf(ss * (1.f / 128.f) + 1e-6f);
        float a0 = k.x * r * knw[e], a1 = k.y * r * knw[e + 1];
        float a2 = k.z * r * knw[e + 2], a3 = k.w * r * knw[e + 3];
        *reinterpret_cast<__half2*>(&g_kf[ob]) =
            __floats2half2_rn(a0 * co0 - a1 * si0, a0 * si0 + a1 * co0);
        *reinterpret_cast<__half2*>(&g_kf[ob + 2]) =
            __floats2half2_rn(a2 * co1 - a3 * si1, a2 * si1 + a3 * co1);
    }
    {
        float4 v = *reinterpret_cast<const float4*>(&g_vp[base + e]);
        *reinterpret_cast<__half2*>(&g_vf[ob])     = __floats2half2_rn(v.x, v.y);
        *reinterpret_cast<__half2*>(&g_vf[ob + 2]) = __floats2half2_rn(v.z, v.w);
    }
}

// ---------------- Flash attention (128q tile, 8 warps, ldmatrix) --------------
__global__ __launch_bounds__(256) void attn_kernel() {
    const int head = blockIdx.y;
    const int qb = blockIdx.x * 128;
    const int tid = threadIdx.x, lane = tid & 31, warp = tid >> 5;
    const int g = lane >> 2, cc2 = (lane & 3) * 2;
    const size_t hb = (size_t)head * NTOK * HD;
    const __half* Qf = g_qf + hb;
    const __half* Kf = g_kf + hb;
    const __half* Vf = g_vf + hb;

    __shared__ __half sK[32][136];
    __shared__ __half sV[32][136];    // row-major [key][d]; transposed via ldmatrix.trans
    const uint32_t skb = smem_u32(&sK[0][0]);
    const uint32_t svb = smem_u32(&sV[0][0]);

    const int krow = (lane >> 3) * 8 + (lane & 7);   // B-frag row for ldmatrix x4

    const int r0 = qb + warp * 16 + g;
    uint32_t qa[8][4];
    #pragma unroll
    for (int ks = 0; ks < 8; ks++) {
        qa[ks][0] = *reinterpret_cast<const uint32_t*>(&Qf[(size_t)r0 * HD + ks * 16 + cc2]);
        qa[ks][1] = *reinterpret_cast<const uint32_t*>(&Qf[(size_t)(r0 + 8) * HD + ks * 16 + cc2]);
        qa[ks][2] = *reinterpret_cast<const uint32_t*>(&Qf[(size_t)r0 * HD + ks * 16 + cc2 + 8]);
        qa[ks][3] = *reinterpret_cast<const uint32_t*>(&Qf[(size_t)(r0 + 8) * HD + ks * 16 + cc2 + 8]);
    }

    float o[16][4] = {};
    float m0v = -1e30f, m1v = -1e30f, l0 = 0.f, l1 = 0.f;

    for (int kt = 0; kt < NTOK / 32; kt++) {
        int kbase = kt * 32;
        #pragma unroll
        for (int i = 0; i < 4; i++) {
            int c = tid + i * 256; int row = c >> 5; int col = (c & 31) * 4;
            size_t ga = (size_t)(kbase + row) * HD + col;
            *reinterpret_cast<uint2*>(&sK[row][col]) = *reinterpret_cast<const uint2*>(Kf + ga);
            *reinterpret_cast<uint2*>(&sV[row][col]) = *reinterpret_cast<const uint2*>(Vf + ga);
        }
        __syncthreads();

        float s[4][4] = {};
        #pragma unroll
        for (int ks = 0; ks < 8; ks++) {
            uint32_t kb0[4], kb1[4];
            ldsm4(kb0[0], kb0[1], kb0[2], kb0[3],
                  skb + (uint32_t)(krow * 136 + ks * 16) * 2);
            ldsm4(kb1[0], kb1[1], kb1[2], kb1[3],
                  skb + (uint32_t)(krow * 136 + ks * 16 + 8) * 2);
            #pragma unroll
            for (int nf = 0; nf < 4; nf++)
                mma16816h(s[nf], qa[ks], kb0[nf], kb1[nf]);
        }

        float mx0 = -1e30f, mx1 = -1e30f;
        #pragma unroll
        for (int nf = 0; nf < 4; nf++) {
            mx0 = fmaxf(mx0, fmaxf(s[nf][0], s[nf][1]));
            mx1 = fmaxf(mx1, fmaxf(s[nf][2], s[nf][3]));
        }
        mx0 = fmaxf(mx0, __shfl_xor_sync(0xffffffffu, mx0, 1));
        mx0 = fmaxf(mx0, __shfl_xor_sync(0xffffffffu, mx0, 2));
        mx1 = fmaxf(mx1, __shfl_xor_sync(0xffffffffu, mx1, 1));
        mx1 = fmaxf(mx1, __shfl_xor_sync(0xffffffffu, mx1, 2));
        float nm0 = fmaxf(m0v, mx0), nm1 = fmaxf(m1v, mx1);
        float c0 = __expf(m0v - nm0), c1 = __expf(m1v - nm1);
        m0v = nm0; m1v = nm1;

        float rs0 = 0.f, rs1 = 0.f;
        #pragma unroll
        for (int nf = 0; nf < 4; nf++) {
            s[nf][0] = __expf(s[nf][0] - nm0); s[nf][1] = __expf(s[nf][1] - nm0);
            s[nf][2] = __expf(s[nf][2] - nm1); s[nf][3] = __expf(s[nf][3] - nm1);
            rs0 += s[nf][0] + s[nf][1];
            rs1 += s[nf][2] + s[nf][3];
        }
        rs0 += __shfl_xor_sync(0xffffffffu, rs0, 1);
        rs0 += __shfl_xor_sync(0xffffffffu, rs0, 2);
        rs1 += __shfl_xor_sync(0xffffffffu, rs1, 1);
        rs1 += __shfl_xor_sync(0xffffffffu, rs1, 2);
        l0 = l0 * c0 + rs0; l1 = l1 * c1 + rs1;
        #pragma unroll
        for (int nf = 0; nf < 16; nf++) {
            o[nf][0] *= c0; o[nf][1] *= c0; o[nf][2] *= c1; o[nf][3] *= c1;
        }

        uint32_t pa[2][4];
        #pragma unroll
        for (int kk = 0; kk < 2; kk++) {
            pa[kk][0] = packh(s[2 * kk][0],     s[2 * kk][1]);
            pa[kk][1] = packh(s[2 * kk][2],     s[2 * kk][3]);
            pa[kk][2] = packh(s[2 * kk + 1][0], s[2 * kk + 1][1]);
            pa[kk][3] = packh(s[2 * kk + 1][2], s[2 * kk + 1][3]);
        }
        #pragma unroll
        for (int kk = 0; kk < 2; kk++) {
            #pragma unroll
            for (int dg = 0; dg < 4; dg++) {
                // V^T fragments via ldmatrix.trans: source rows = keys, cols = d
                uint32_t a0 = svb + (uint32_t)((kk * 16 + (lane & 7)) * 136
                                               + dg * 32 + (lane >> 3) * 8) * 2;
                uint32_t a1 = svb + (uint32_t)((kk * 16 + 8 + (lane & 7)) * 136
                                               + dg * 32 + (lane >> 3) * 8) * 2;
                uint32_t vb0[4], vb1[4];
                ldsm4t(vb0[0], vb0[1], vb0[2], vb0[3], a0);
                ldsm4t(vb1[0], vb1[1], vb1[2], vb1[3], a1);
                #pragma unroll
                for (int j = 0; j < 4; j++)
                    mma16816h(o[dg * 4 + j], pa[kk], vb0[j], vb1[j]);
            }
        }
        __syncthreads();
    }

    float i0 = 1.f / l0, i1 = 1.f / l1;
    #pragma unroll
    for (int nf = 0; nf < 16; nf++) {
        int col = head * HD + nf * 8 + cc2;
        *reinterpret_cast<uint32_t*>(&g_aof[(size_t)r0 * CDIM + col]) =
            packh(o[nf][0] * i0, o[nf][1] * i0);
        *reinterpret_cast<uint32_t*>(&g_aof[(size_t)(r0 + 8) * CDIM + col]) =
            packh(o[nf][2] * i1, o[nf][3] * i1);
    }
}

// ---------------- launch ------------------------------------------------------
extern "C" void kernel_launch(void* const* d_in, const int* in_sizes, int n_in,
                              void* d_out, int out_size) {
    const float* x   = (const float*)d_in[0];
    const float* Wq  = (const float*)d_in[1];
    const float* bq  = (const float*)d_in[2];
    const float* Wk  = (const float*)d_in[3];
    const float* bk  = (const float*)d_in[4];
    const float* Wv  = (const float*)d_in[5];
    const float* bv  = (const float*)d_in[6];
    const float* qnw = (const float*)d_in[7];
    const float* knw = (const float*)d_in[8];
    const float* Wo  = (const float*)d_in[9];
    const float* bo  = (const float*)d_in[10];
    float* out = (float*)d_out;

    cudaFuncSetAttribute(gemm_f16<0>, cudaFuncAttributeMaxDynamicSharedMemorySize, GSMEM);
    cudaFuncSetAttribute(gemm_f16<1>, cudaFuncAttributeMaxDynamicSharedMemorySize, GSMEM);
    cudaFuncSetAttribute(gemm_f16<2>, cudaFuncAttributeMaxDynamicSharedMemorySize, GSMEM);
    cudaFuncSetAttribute(gemm_f16<3>, cudaFuncAttributeMaxDynamicSharedMemorySize, GSMEM);

    const int NW = CDIM * CDIM;
    const int NX = NTOK * CDIM;
    cvt_f16<0><<<NX / 1024, 256>>>(x, NX);
    cvt_f16<1><<<NW / 1024, 256>>>(Wq, NW);
    cvt_f16<2><<<NW / 1024, 256>>>(Wk, NW);
    cvt_f16<3><<<NW / 1024, 256>>>(Wv, NW);
    cvt_f16<4><<<NW / 1024, 256>>>(Wo, NW);

    dim3 ggrid(CDIM / 128, NTOK / 128);
    gemm_f16<0><<<ggrid, 256, GSMEM>>>(bq, nullptr);
    gemm_f16<1><<<ggrid, 256, GSMEM>>>(bk, nullptr);
    gemm_f16<2><<<ggrid, 256, GSMEM>>>(bv, nullptr);

    normrope<<<NTOK * HEADS / 4, 128>>>(qnw, knw);

    dim3 agrid(NTOK / 128, HEADS);
    attn_kernel<<<agrid, 256>>>();

    gemm_f16<3><<<ggrid, 256, GSMEM>>>(bo, out);
}

// round 16
// speedup vs baseline: 4.5205x; 1.1880x over previous
// r14-64key-fusedqkv (resubmission 3; prior two attempts died in broker pre-exec)
#include <cuda_runtime.h>
#include <cuda_bf16.h>
#include <cuda_fp16.h>
#include <cstdint>
#include <math.h>

// Problem constants (fixed by setup_inputs: B=1, T=8, H=16, W=32)
#define NTOK 4096
#define CDIM 2048
#define HEADS 16
#define HD 128

// ---------------- scratch (device globals; no allocations allowed) ----------
__device__ __half g_xf[NTOK * CDIM];
__device__ __half g_Wqf[CDIM * CDIM];
__device__ __half g_Wkf[CDIM * CDIM];
__device__ __half g_Wvf[CDIM * CDIM];
__device__ __half g_Wof[CDIM * CDIM];
__device__ float g_qp[NTOK * CDIM];
__device__ float g_kp[NTOK * CDIM];
__device__ float g_vp[NTOK * CDIM];
// head-major fp16 q/k/v for attention (q has 1/sqrt(HD) folded in)
__device__ __half g_qf[NTOK * CDIM];
__device__ __half g_kf[NTOK * CDIM];
__device__ __half g_vf[NTOK * CDIM];
// token-major fp16 attention output
__device__ __half g_aof[NTOK * CDIM];

// ---------------- helpers ----------------------------------------------------
__device__ __forceinline__ void mma16816h(float* c, const uint32_t* a, uint32_t b0, uint32_t b1) {
    asm volatile(
        "mma.sync.aligned.m16n8k16.row.col.f32.f16.f16.f32 "
        "{%0,%1,%2,%3}, {%4,%5,%6,%7}, {%8,%9}, {%0,%1,%2,%3};\n"
        : "+f"(c[0]), "+f"(c[1]), "+f"(c[2]), "+f"(c[3])
        : "r"(a[0]), "r"(a[1]), "r"(a[2]), "r"(a[3]), "r"(b0), "r"(b1));
}

__device__ __forceinline__ void ldsm4(uint32_t& r0, uint32_t& r1, uint32_t& r2, uint32_t& r3,
                                      uint32_t addr) {
    asm volatile("ldmatrix.sync.aligned.m8n8.x4.shared.b16 {%0,%1,%2,%3}, [%4];"
                 : "=r"(r0), "=r"(r1), "=r"(r2), "=r"(r3) : "r"(addr));
}
__device__ __forceinline__ void ldsm4t(uint32_t& r0, uint32_t& r1, uint32_t& r2, uint32_t& r3,
                                       uint32_t addr) {
    asm volatile("ldmatrix.sync.aligned.m8n8.x4.trans.shared.b16 {%0,%1,%2,%3}, [%4];"
                 : "=r"(r0), "=r"(r1), "=r"(r2), "=r"(r3) : "r"(addr));
}

__device__ __forceinline__ uint32_t packh(float a, float b) {
    __half2 h = __floats2half2_rn(a, b);
    return *reinterpret_cast<uint32_t*>(&h);
}

__device__ __forceinline__ uint32_t smem_u32(const void* p) {
    uint32_t a;
    asm("{ .reg .u64 t; cvta.to.shared.u64 t, %1; cvt.u32.u64 %0, t; }" : "=r"(a) : "l"(p));
    return a;
}
__device__ __forceinline__ void cpasync16(uint32_t dst, const void* src) {
    asm volatile("cp.async.cg.shared.global [%0], [%1], 16;" :: "r"(dst), "l"(src));
}
__device__ __forceinline__ void cpcommit() {
    asm volatile("cp.async.commit_group;" ::: "memory");
}
template <int N>
__device__ __forceinline__ void cpwait() {
    asm volatile("cp.async.wait_group %0;" :: "n"(N) : "memory");
}

// ---------------- fp32 -> fp16 conversion -------------------------------------
template <int SEL>
__global__ void cvt_f16(const float* __restrict__ src, int n) {
    __half* dst = (SEL == 0) ? g_xf : (SEL == 1) ? g_Wqf
                : (SEL == 2) ? g_Wkf : (SEL == 3) ? g_Wvf : g_Wof;
    int i = (blockIdx.x * blockDim.x + threadIdx.x) * 4;
    if (i < n) {
        float4 v = *reinterpret_cast<const float4*>(src + i);
        *reinterpret_cast<__half2*>(dst + i)     = __floats2half2_rn(v.x, v.y);
        *reinterpret_cast<__half2*>(dst + i + 2) = __floats2half2_rn(v.z, v.w);
    }
}

// ---------------- fp16 GEMM: cp.async 3-stage + ldmatrix ----------------------
// SEL 0: fused QKV (A = g_xf, grid.x = 48, per-block W/bias/out select)
// SEL 1: O projection (A = g_aof, grid.x = 16)
#define KC 32
#define NST 3
#define TROW 40                          // padded row length (halves)
#define TILEPAD (128 * TROW * 2)         // 10240 B per tile
#define STAGEB (2 * TILEPAD)             // A, B
#define GSMEM (NST * STAGEB)             // 61440 B

template <int SEL>
__global__ __launch_bounds__(256) void gemm_f16(const float* __restrict__ b0p,
                                                const float* __restrict__ b1p,
                                                const float* __restrict__ b2p,
                                                float* __restrict__ outp)
{
    const __half* __restrict__ A = (SEL == 0) ? g_xf : g_aof;
    const int nt = blockIdx.x;
    const __half* __restrict__ B;
    float* __restrict__ C;
    const float* __restrict__ bias;
    int n0;
    if (SEL == 0) {
        int mat = nt >> 4;   // 0=Q, 1=K, 2=V
        B    = (mat == 0) ? g_Wqf : (mat == 1) ? g_Wkf : g_Wvf;
        C    = (mat == 0) ? g_qp  : (mat == 1) ? g_kp  : g_vp;
        bias = (mat == 0) ? b0p   : (mat == 1) ? b1p   : b2p;
        n0 = (nt & 15) * 128;
    } else {
        B = g_Wof; C = outp; bias = b0p;
        n0 = nt * 128;
    }

    extern __shared__ char dsm[];
    const uint32_t sb = smem_u32(dsm);

    const int tid = threadIdx.x, lane = tid & 31, warp = tid >> 5;
    const int wm = warp >> 2, wn = warp & 3;     // 2x4 warp grid, 64x32 warp tile
    const int m0 = blockIdx.y * 128;
    const int g = lane >> 2, cc2 = (lane & 3) * 2;

    const int arow = (lane & 7) + ((lane >> 3) & 1) * 8;
    const int acol8 = (lane >> 4) * 8;
    const int brow = wn * 32 + (lane >> 3) * 8 + (lane & 7);

    auto issue = [&](int kt, int s) {
        #pragma unroll
        for (int j = 0; j < 4; j++) {
            int u = tid + j * 256;
            int t = u >> 9;
            int uu = u & 511;
            int row = uu >> 2;
            int c16 = uu & 3;
            const __half* src = (t == 0) ? A : B;
            int rbase = (t == 0) ? m0 : n0;
            uint32_t dst = sb + s * STAGEB + t * TILEPAD + row * (TROW * 2) + c16 * 16;
            cpasync16(dst, src + (size_t)(rbase + row) * CDIM + kt * KC + c16 * 8);
        }
        cpcommit();
    };

    issue(0, 0);
    issue(1, 1);

    float acc[4][4][4] = {};
    const int NKT = CDIM / KC;   // 64

    for (int kt = 0; kt < NKT; kt++) {
        const int s = kt % NST;
        if (kt == NKT - 1) cpwait<0>(); else cpwait<1>();
        __syncthreads();
        if (kt + 2 < NKT) issue(kt + 2, (kt + 2) % NST);

        const uint32_t aoff = sb + s * STAGEB;
        const uint32_t boff = aoff + TILEPAD;

        #pragma unroll
        for (int ks = 0; ks < 2; ks++) {
            uint32_t b0v[4], b1v[4];
            ldsm4(b0v[0], b0v[1], b0v[2], b0v[3],
                  boff + (uint32_t)(brow * TROW + ks * 16) * 2);
            ldsm4(b1v[0], b1v[1], b1v[2], b1v[3],
                  boff + (uint32_t)(brow * TROW + ks * 16 + 8) * 2);
            #pragma unroll
            for (int mf = 0; mf < 4; mf++) {
                uint32_t a[4];
                ldsm4(a[0], a[1], a[2], a[3],
                      aoff + (uint32_t)((wm * 64 + mf * 16 + arow) * TROW + ks * 16 + acol8) * 2);
                #pragma unroll
                for (int nf = 0; nf < 4; nf++)
                    mma16816h(acc[mf][nf], a, b0v[nf], b1v[nf]);
            }
        }
    }

    #pragma unroll
    for (int mf = 0; mf < 4; mf++) {
        int r0 = m0 + wm * 64 + mf * 16 + g;
        #pragma unroll
        for (int nf = 0; nf < 4; nf++) {
            int col = n0 + wn * 32 + nf * 8 + cc2;
            float b0v = bias[col], b1v = bias[col + 1];
            float2 o0; o0.x = acc[mf][nf][0] + b0v; o0.y = acc[mf][nf][1] + b1v;
            float2 o1; o1.x = acc[mf][nf][2] + b0v; o1.y = acc[mf][nf][3] + b1v;
            *reinterpret_cast<float2*>(C + (size_t)r0 * CDIM + col)       = o0;
            *reinterpret_cast<float2*>(C + (size_t)(r0 + 8) * CDIM + col) = o1;
        }
    }
}

// ---------------- RMSNorm + 3D RoPE + fp16 pack -------------------------------
__device__ __forceinline__ float rope_ang(int p, int token) {
    int t = token >> 9;
    int rem = token & 511;
    int h = rem >> 5, w = rem & 31;
    float pos, expo, d;
    if (p < 22)      { pos = (float)t; expo = (float)(2 * p);        d = 44.f; }
    else if (p < 43) { pos = (float)h; expo = (float)(2 * (p - 22)); d = 42.f; }
    else             { pos = (float)w; expo = (float)(2 * (p - 43)); d = 42.f; }
    return pos * powf(10000.f, -expo / d);
}

__global__ __launch_bounds__(128) void normrope(const float* __restrict__ qnw,
                                                const float* __restrict__ knw) {
    int idx = blockIdx.x * 4 + (threadIdx.x >> 5);
    int lane = threadIdx.x & 31;
    int token = idx >> 4, head = idx & 15;
    int base = token * CDIM + head * HD;
    int e = lane * 4;
    const float SC = 0.08838834764831845f;  // 1/sqrt(128) folded into q

    float ang0 = rope_ang(lane * 2, token);
    float ang1 = rope_ang(lane * 2 + 1, token);
    float co0 = cosf(ang0), si0 = sinf(ang0);
    float co1 = cosf(ang1), si1 = sinf(ang1);
    int ob = (head * NTOK + token) * HD + e;

    {
        float4 q = *reinterpret_cast<const float4*>(&g_qp[base + e]);
        float ss = q.x * q.x + q.y * q.y + q.z * q.z + q.w * q.w;
        #pragma unroll
        for (int o = 16; o; o >>= 1) ss += __shfl_xor_sync(0xffffffffu, ss, o);
        float r = rsqrtf(ss * (1.f / 128.f) + 1e-6f);
        float a0 = q.x * r * qnw[e], a1 = q.y * r * qnw[e + 1];
        float a2 = q.z * r * qnw[e + 2], a3 = q.w * r * qnw[e + 3];
        *reinterpret_cast<__half2*>(&g_qf[ob]) =
            __floats2half2_rn((a0 * co0 - a1 * si0) * SC, (a0 * si0 + a1 * co0) * SC);
        *reinterpret_cast<__half2*>(&g_qf[ob + 2]) =
            __floats2half2_rn((a2 * co1 - a3 * si1) * SC, (a2 * si1 + a3 * co1) * SC);
    }
    {
        float4 k = *reinterpret_cast<const float4*>(&g_kp[base + e]);
        float ss = k.x * k.x + k.y * k.y + k.z * k.z + k.w * k.w;
        #pragma unroll
        for (int o = 16; o; o >>= 1) ss += __shfl_xor_sync(0xffffffffu, ss, o);
        float r = rsqrtf(ss * (1.f / 128.f) + 1e-6f);
        float a0 = k.x * r * knw[e], a1 = k.y * r * knw[e + 1];
        float a2 = k.z * r * knw[e + 2], a3 = k.w * r * knw[e + 3];
        *reinterpret_cast<__half2*>(&g_kf[ob]) =
            __floats2half2_rn(a0 * co0 - a1 * si0, a0 * si0 + a1 * co0);
        *reinterpret_cast<__half2*>(&g_kf[ob + 2]) =
            __floats2half2_rn(a2 * co1 - a3 * si1, a2 * si1 + a3 * co1);
    }
    {
        float4 v = *reinterpret_cast<const float4*>(&g_vp[base + e]);
        *reinterpret_cast<__half2*>(&g_vf[ob])     = __floats2half2_rn(v.x, v.y);
        *reinterpret_cast<__half2*>(&g_vf[ob + 2]) = __floats2half2_rn(v.z, v.w);
    }
}

// ---------------- Flash attention (128q tile, 64-key stripes, ldmatrix) -------
__global__ __launch_bounds__(256, 1) void attn_kernel() {
    const int head = blockIdx.y;
    const int qb = blockIdx.x * 128;
    const int tid = threadIdx.x, lane = tid & 31, warp = tid >> 5;
    const int g = lane >> 2, cc2 = (lane & 3) * 2;
    const size_t hb = (size_t)head * NTOK * HD;
    const __half* Qf = g_qf + hb;
    const __half* Kf = g_kf + hb;
    const __half* Vf = g_vf + hb;

    __shared__ __half sK[64][136];
    __shared__ __half sV[64][136];    // row-major [key][d]; transposed via ldmatrix.trans
    const uint32_t skb = smem_u32(&sK[0][0]);
    const uint32_t svb = smem_u32(&sV[0][0]);

    const int krow = (lane >> 3) * 8 + (lane & 7);   // B-frag row for ldmatrix x4

    const int r0 = qb + warp * 16 + g;
    uint32_t qa[8][4];
    #pragma unroll
    for (int ks = 0; ks < 8; ks++) {
        qa[ks][0] = *reinterpret_cast<const uint32_t*>(&Qf[(size_t)r0 * HD + ks * 16 + cc2]);
        qa[ks][1] = *reinterpret_cast<const uint32_t*>(&Qf[(size_t)(r0 + 8) * HD + ks * 16 + cc2]);
        qa[ks][2] = *reinterpret_cast<const uint32_t*>(&Qf[(size_t)r0 * HD + ks * 16 + cc2 + 8]);
        qa[ks][3] = *reinterpret_cast<const uint32_t*>(&Qf[(size_t)(r0 + 8) * HD + ks * 16 + cc2 + 8]);
    }

    float o[16][4] = {};
    float m0v = -1e30f, m1v = -1e30f, l0 = 0.f, l1 = 0.f;

    for (int kt = 0; kt < NTOK / 64; kt++) {
        int kbase = kt * 64;
        #pragma unroll
        for (int i = 0; i < 8; i++) {
            int c = tid + i * 256; int row = c >> 5; int col = (c & 31) * 4;
            size_t ga = (size_t)(kbase + row) * HD + col;
            *reinterpret_cast<uint2*>(&sK[row][col]) = *reinterpret_cast<const uint2*>(Kf + ga);
            *reinterpret_cast<uint2*>(&sV[row][col]) = *reinterpret_cast<const uint2*>(Vf + ga);
        }
        __syncthreads();

        float s[8][4] = {};
        #pragma unroll
        for (int ks = 0; ks < 8; ks++) {
            uint32_t kb0[4], kb1[4], kc0[4], kc1[4];
            ldsm4(kb0[0], kb0[1], kb0[2], kb0[3],
                  skb + (uint32_t)(krow * 136 + ks * 16) * 2);
            ldsm4(kb1[0], kb1[1], kb1[2], kb1[3],
                  skb + (uint32_t)(krow * 136 + ks * 16 + 8) * 2);
            ldsm4(kc0[0], kc0[1], kc0[2], kc0[3],
                  skb + (uint32_t)((32 + krow) * 136 + ks * 16) * 2);
            ldsm4(kc1[0], kc1[1], kc1[2], kc1[3],
                  skb + (uint32_t)((32 + krow) * 136 + ks * 16 + 8) * 2);
            #pragma unroll
            for (int nf = 0; nf < 4; nf++) {
                mma16816h(s[nf],     qa[ks], kb0[nf], kb1[nf]);
                mma16816h(s[nf + 4], qa[ks], kc0[nf], kc1[nf]);
            }
        }

        float mx0 = -1e30f, mx1 = -1e30f;
        #pragma unroll
        for (int nf = 0; nf < 8; nf++) {
            mx0 = fmaxf(mx0, fmaxf(s[nf][0], s[nf][1]));
            mx1 = fmaxf(mx1, fmaxf(s[nf][2], s[nf][3]));
        }
        mx0 = fmaxf(mx0, __shfl_xor_sync(0xffffffffu, mx0, 1));
        mx0 = fmaxf(mx0, __shfl_xor_sync(0xffffffffu, mx0, 2));
        mx1 = fmaxf(mx1, __shfl_xor_sync(0xffffffffu, mx1, 1));
        mx1 = fmaxf(mx1, __shfl_xor_sync(0xffffffffu, mx1, 2));
        float nm0 = fmaxf(m0v, mx0), nm1 = fmaxf(m1v, mx1);
        float c0 = __expf(m0v - nm0), c1 = __expf(m1v - nm1);
        m0v = nm0; m1v = nm1;

        float rs0 = 0.f, rs1 = 0.f;
        #pragma unroll
        for (int nf = 0; nf < 8; nf++) {
            s[nf][0] = __expf(s[nf][0] - nm0); s[nf][1] = __expf(s[nf][1] - nm0);
            s[nf][2] = __expf(s[nf][2] - nm1); s[nf][3] = __expf(s[nf][3] - nm1);
            rs0 += s[nf][0] + s[nf][1];
            rs1 += s[nf][2] + s[nf][3];
        }
        rs0 += __shfl_xor_sync(0xffffffffu, rs0, 1);
        rs0 += __shfl_xor_sync(0xffffffffu, rs0, 2);
        rs1 += __shfl_xor_sync(0xffffffffu, rs1, 1);
        rs1 += __shfl_xor_sync(0xffffffffu, rs1, 2);
        l0 = l0 * c0 + rs0; l1 = l1 * c1 + rs1;
        #pragma unroll
        for (int nf = 0; nf < 16; nf++) {
            o[nf][0] *= c0; o[nf][1] *= c0; o[nf][2] *= c1; o[nf][3] *= c1;
        }

        uint32_t pa[4][4];
        #pragma unroll
        for (int kk = 0; kk < 4; kk++) {
            pa[kk][0] = packh(s[2 * kk][0],     s[2 * kk][1]);
            pa[kk][1] = packh(s[2 * kk][2],     s[2 * kk][3]);
            pa[kk][2] = packh(s[2 * kk + 1][0], s[2 * kk + 1][1]);
            pa[kk][3] = packh(s[2 * kk + 1][2], s[2 * kk + 1][3]);
        }
        #pragma unroll
        for (int kk = 0; kk < 4; kk++) {
            #pragma unroll
            for (int dg = 0; dg < 4; dg++) {
                uint32_t a0 = svb + (uint32_t)((kk * 16 + (lane & 7)) * 136
                                               + dg * 32 + (lane >> 3) * 8) * 2;
                uint32_t a1 = svb + (uint32_t)((kk * 16 + 8 + (lane & 7)) * 136
                                               + dg * 32 + (lane >> 3) * 8) * 2;
                uint32_t vb0[4], vb1[4];
                ldsm4t(vb0[0], vb0[1], vb0[2], vb0[3], a0);
                ldsm4t(vb1[0], vb1[1], vb1[2], vb1[3], a1);
                #pragma unroll
                for (int j = 0; j < 4; j++)
                    mma16816h(o[dg * 4 + j], pa[kk], vb0[j], vb1[j]);
            }
        }
        __syncthreads();
    }

    float i0 = 1.f / l0, i1 = 1.f / l1;
    #pragma unroll
    for (int nf = 0; nf < 16; nf++) {
        int col = head * HD + nf * 8 + cc2;
        *reinterpret_cast<uint32_t*>(&g_aof[(size_t)r0 * CDIM + col]) =
            packh(o[nf][0] * i0, o[nf][1] * i0);
        *reinterpret_cast<uint32_t*>(&g_aof[(size_t)(r0 + 8) * CDIM + col]) =
            packh(o[nf][2] * i1, o[nf][3] * i1);
    }
}

// ---------------- launch ------------------------------------------------------
extern "C" void kernel_launch(void* const* d_in, const int* in_sizes, int n_in,
                              void* d_out, int out_size) {
    const float* x   = (const float*)d_in[0];
    const float* Wq  = (const float*)d_in[1];
    const float* bq  = (const float*)d_in[2];
    const float* Wk  = (const float*)d_in[3];
    const float* bk  = (const float*)d_in[4];
    const float* Wv  = (const float*)d_in[5];
    const float* bv  = (const float*)d_in[6];
    const float* qnw = (const float*)d_in[7];
    const float* knw = (const float*)d_in[8];
    const float* Wo  = (const float*)d_in[9];
    const float* bo  = (const float*)d_in[10];
    float* out = (float*)d_out;

    cudaFuncSetAttribute(gemm_f16<0>, cudaFuncAttributeMaxDynamicSharedMemorySize, GSMEM);
    cudaFuncSetAttribute(gemm_f16<1>, cudaFuncAttributeMaxDynamicSharedMemorySize, GSMEM);

    const int NW = CDIM * CDIM;
    const int NX = NTOK * CDIM;
    cvt_f16<0><<<NX / 1024, 256>>>(x, NX);
    cvt_f16<1><<<NW / 1024, 256>>>(Wq, NW);
    cvt_f16<2><<<NW / 1024, 256>>>(Wk, NW);
    cvt_f16<3><<<NW / 1024, 256>>>(Wv, NW);
    cvt_f16<4><<<NW / 1024, 256>>>(Wo, NW);

    gemm_f16<0><<<dim3(48, 32), 256, GSMEM>>>(bq, bk, bv, nullptr);

    normrope<<<NTOK * HEADS / 4, 128>>>(qnw, knw);

    dim3 agrid(NTOK / 128, HEADS);
    attn_kernel<<<agrid, 256>>>();

    gemm_f16<1><<<dim3(16, 32), 256, GSMEM>>>(bo, nullptr, nullptr, out);
}

// round 17
// speedup vs baseline: 5.0065x; 1.1075x over previous
// r17: attn cp.async 3-stage + exp2 fold + merged converts
#include <cuda_runtime.h>
#include <cuda_bf16.h>
#include <cuda_fp16.h>
#include <cstdint>
#include <math.h>

#define NTOK 4096
#define CDIM 2048
#define HEADS 16
#define HD 128

// ---------------- scratch (device globals; no allocations allowed) ----------
__device__ __half g_xf[NTOK * CDIM];
__device__ __half g_Wqf[CDIM * CDIM];
__device__ __half g_Wkf[CDIM * CDIM];
__device__ __half g_Wvf[CDIM * CDIM];
__device__ __half g_Wof[CDIM * CDIM];
__device__ float g_qp[NTOK * CDIM];
__device__ float g_kp[NTOK * CDIM];
__device__ float g_vp[NTOK * CDIM];
// head-major fp16 q/k/v (q has log2e/sqrt(HD) folded in)
__device__ __half g_qf[NTOK * CDIM];
__device__ __half g_kf[NTOK * CDIM];
__device__ __half g_vf[NTOK * CDIM];
__device__ __half g_aof[NTOK * CDIM];

// ---------------- helpers ----------------------------------------------------
__device__ __forceinline__ void mma16816h(float* c, const uint32_t* a, uint32_t b0, uint32_t b1) {
    asm volatile(
        "mma.sync.aligned.m16n8k16.row.col.f32.f16.f16.f32 "
        "{%0,%1,%2,%3}, {%4,%5,%6,%7}, {%8,%9}, {%0,%1,%2,%3};\n"
        : "+f"(c[0]), "+f"(c[1]), "+f"(c[2]), "+f"(c[3])
        : "r"(a[0]), "r"(a[1]), "r"(a[2]), "r"(a[3]), "r"(b0), "r"(b1));
}

__device__ __forceinline__ void ldsm4(uint32_t& r0, uint32_t& r1, uint32_t& r2, uint32_t& r3,
                                      uint32_t addr) {
    asm volatile("ldmatrix.sync.aligned.m8n8.x4.shared.b16 {%0,%1,%2,%3}, [%4];"
                 : "=r"(r0), "=r"(r1), "=r"(r2), "=r"(r3) : "r"(addr));
}
__device__ __forceinline__ void ldsm4t(uint32_t& r0, uint32_t& r1, uint32_t& r2, uint32_t& r3,
                                       uint32_t addr) {
    asm volatile("ldmatrix.sync.aligned.m8n8.x4.trans.shared.b16 {%0,%1,%2,%3}, [%4];"
                 : "=r"(r0), "=r"(r1), "=r"(r2), "=r"(r3) : "r"(addr));
}

__device__ __forceinline__ uint32_t packh(float a, float b) {
    __half2 h = __floats2half2_rn(a, b);
    return *reinterpret_cast<uint32_t*>(&h);
}

__device__ __forceinline__ uint32_t smem_u32(const void* p) {
    uint32_t a;
    asm("{ .reg .u64 t; cvta.to.shared.u64 t, %1; cvt.u32.u64 %0, t; }" : "=r"(a) : "l"(p));
    return a;
}
__device__ __forceinline__ void cpasync16(uint32_t dst, const void* src) {
    asm volatile("cp.async.cg.shared.global [%0], [%1], 16;" :: "r"(dst), "l"(src));
}
__device__ __forceinline__ void cpcommit() {
    asm volatile("cp.async.commit_group;" ::: "memory");
}
template <int N>
__device__ __forceinline__ void cpwait() {
    asm volatile("cp.async.wait_group %0;" :: "n"(N) : "memory");
}

// ---------------- merged fp32 -> fp16 conversion ------------------------------
// layout: [x (NX) | Wq | Wk | Wv | Wo] — NW = 2^22 so region math is bitwise
#define NXE (NTOK * CDIM)
#define NWE (CDIM * CDIM)
__global__ void cvt_all(const float* __restrict__ x,  const float* __restrict__ Wq,
                        const float* __restrict__ Wk, const float* __restrict__ Wv,
                        const float* __restrict__ Wo) {
    int i = (blockIdx.x * blockDim.x + threadIdx.x) * 4;
    const float* src; __half* dst; int off;
    if (i < NXE) { src = x; dst = g_xf; off = i; }
    else {
        int j = i - NXE;
        int w = j >> 22;            // NWE == 1<<22
        off = j & (NWE - 1);
        src = (w == 0) ? Wq : (w == 1) ? Wk : (w == 2) ? Wv : Wo;
        dst = (w == 0) ? g_Wqf : (w == 1) ? g_Wkf : (w == 2) ? g_Wvf : g_Wof;
    }
    float4 v = *reinterpret_cast<const float4*>(src + off);
    *reinterpret_cast<__half2*>(dst + off)     = __floats2half2_rn(v.x, v.y);
    *reinterpret_cast<__half2*>(dst + off + 2) = __floats2half2_rn(v.z, v.w);
}

// ---------------- fp16 GEMM: cp.async 3-stage + ldmatrix ----------------------
#define KC 32
#define NST 3
#define TROW 40
#define TILEPAD (128 * TROW * 2)
#define STAGEB (2 * TILEPAD)
#define GSMEM (NST * STAGEB)

template <int SEL>
__global__ __launch_bounds__(256) void gemm_f16(const float* __restrict__ b0p,
                                                const float* __restrict__ b1p,
                                                const float* __restrict__ b2p,
                                                float* __restrict__ outp)
{
    const __half* __restrict__ A = (SEL == 0) ? g_xf : g_aof;
    const int nt = blockIdx.x;
    const __half* __restrict__ B;
    float* __restrict__ C;
    const float* __restrict__ bias;
    int n0;
    if (SEL == 0) {
        int mat = nt >> 4;
        B    = (mat == 0) ? g_Wqf : (mat == 1) ? g_Wkf : g_Wvf;
        C    = (mat == 0) ? g_qp  : (mat == 1) ? g_kp  : g_vp;
        bias = (mat == 0) ? b0p   : (mat == 1) ? b1p   : b2p;
        n0 = (nt & 15) * 128;
    } else {
        B = g_Wof; C = outp; bias = b0p;
        n0 = nt * 128;
    }

    extern __shared__ char dsm[];
    const uint32_t sb = smem_u32(dsm);

    const int tid = threadIdx.x, lane = tid & 31, warp = tid >> 5;
    const int wm = warp >> 2, wn = warp & 3;
    const int m0 = blockIdx.y * 128;
    const int g = lane >> 2, cc2 = (lane & 3) * 2;

    const int arow = (lane & 7) + ((lane >> 3) & 1) * 8;
    const int acol8 = (lane >> 4) * 8;
    const int brow = wn * 32 + (lane >> 3) * 8 + (lane & 7);

    auto issue = [&](int kt, int s) {
        #pragma unroll
        for (int j = 0; j < 4; j++) {
            int u = tid + j * 256;
            int t = u >> 9;
            int uu = u & 511;
            int row = uu >> 2;
            int c16 = uu & 3;
            const __half* src = (t == 0) ? A : B;
            int rbase = (t == 0) ? m0 : n0;
            uint32_t dst = sb + s * STAGEB + t * TILEPAD + row * (TROW * 2) + c16 * 16;
            cpasync16(dst, src + (size_t)(rbase + row) * CDIM + kt * KC + c16 * 8);
        }
        cpcommit();
    };

    issue(0, 0);
    issue(1, 1);

    float acc[4][4][4] = {};
    const int NKT = CDIM / KC;

    for (int kt = 0; kt < NKT; kt++) {
        const int s = kt % NST;
        if (kt == NKT - 1) cpwait<0>(); else cpwait<1>();
        __syncthreads();
        if (kt + 2 < NKT) issue(kt + 2, (kt + 2) % NST);

        const uint32_t aoff = sb + s * STAGEB;
        const uint32_t boff = aoff + TILEPAD;

        #pragma unroll
        for (int ks = 0; ks < 2; ks++) {
            uint32_t b0v[4], b1v[4];
            ldsm4(b0v[0], b0v[1], b0v[2], b0v[3],
                  boff + (uint32_t)(brow * TROW + ks * 16) * 2);
            ldsm4(b1v[0], b1v[1], b1v[2], b1v[3],
                  boff + (uint32_t)(brow * TROW + ks * 16 + 8) * 2);
            #pragma unroll
            for (int mf = 0; mf < 4; mf++) {
                uint32_t a[4];
                ldsm4(a[0], a[1], a[2], a[3],
                      aoff + (uint32_t)((wm * 64 + mf * 16 + arow) * TROW + ks * 16 + acol8) * 2);
                #pragma unroll
                for (int nf = 0; nf < 4; nf++)
                    mma16816h(acc[mf][nf], a, b0v[nf], b1v[nf]);
            }
        }
    }

    #pragma unroll
    for (int mf = 0; mf < 4; mf++) {
        int r0 = m0 + wm * 64 + mf * 16 + g;
        #pragma unroll
        for (int nf = 0; nf < 4; nf++) {
            int col = n0 + wn * 32 + nf * 8 + cc2;
            float b0v = bias[col], b1v = bias[col + 1];
            float2 o0; o0.x = acc[mf][nf][0] + b0v; o0.y = acc[mf][nf][1] + b1v;
            float2 o1; o1.x = acc[mf][nf][2] + b0v; o1.y = acc[mf][nf][3] + b1v;
            *reinterpret_cast<float2*>(C + (size_t)r0 * CDIM + col)       = o0;
            *reinterpret_cast<float2*>(C + (size_t)(r0 + 8) * CDIM + col) = o1;
        }
    }
}

// ---------------- RMSNorm + 3D RoPE + fp16 pack -------------------------------
__device__ __forceinline__ float rope_ang(int p, int token) {
    int t = token >> 9;
    int rem = token & 511;
    int h = rem >> 5, w = rem & 31;
    float pos, expo, d;
    if (p < 22)      { pos = (float)t; expo = (float)(2 * p);        d = 44.f; }
    else if (p < 43) { pos = (float)h; expo = (float)(2 * (p - 22)); d = 42.f; }
    else             { pos = (float)w; expo = (float)(2 * (p - 43)); d = 42.f; }
    return pos * powf(10000.f, -expo / d);
}

__global__ __launch_bounds__(128) void normrope(const float* __restrict__ qnw,
                                                const float* __restrict__ knw) {
    int idx = blockIdx.x * 4 + (threadIdx.x >> 5);
    int lane = threadIdx.x & 31;
    int token = idx >> 4, head = idx & 15;
    int base = token * CDIM + head * HD;
    int e = lane * 4;
    // 1/sqrt(128) * log2(e), folded into q so softmax can use exp2 directly
    const float SC = 0.08838834764831845f * 1.4426950408889634f;

    float ang0 = rope_ang(lane * 2, token);
    float ang1 = rope_ang(lane * 2 + 1, token);
    float co0 = cosf(ang0), si0 = sinf(ang0);
    float co1 = cosf(ang1), si1 = sinf(ang1);
    int ob = (head * NTOK + token) * HD + e;

    {
        float4 q = *reinterpret_cast<const float4*>(&g_qp[base + e]);
        float ss = q.x * q.x + q.y * q.y + q.z * q.z + q.w * q.w;
        #pragma unroll
        for (int o = 16; o; o >>= 1) ss += __shfl_xor_sync(0xffffffffu, ss, o);
        float r = rsqrtf(ss * (1.f / 128.f) + 1e-6f);
        float a0 = q.x * r * qnw[e], a1 = q.y * r * qnw[e + 1];
        float a2 = q.z * r * qnw[e + 2], a3 = q.w * r * qnw[e + 3];
        *reinterpret_cast<__half2*>(&g_qf[ob]) =
            __floats2half2_rn((a0 * co0 - a1 * si0) * SC, (a0 * si0 + a1 * co0) * SC);
        *reinterpret_cast<__half2*>(&g_qf[ob + 2]) =
            __floats2half2_rn((a2 * co1 - a3 * si1) * SC, (a2 * si1 + a3 * co1) * SC);
    }
    {
        float4 k = *reinterpret_cast<const float4*>(&g_kp[base + e]);
        float ss = k.x * k.x + k.y * k.y + k.z * k.z + k.w * k.w;
        #pragma unroll
        for (int o = 16; o; o >>= 1) ss += __shfl_xor_sync(0xffffffffu, ss, o);
        float r = rsqrtf(ss * (1.f / 128.f) + 1e-6f);
        float a0 = k.x * r * knw[e], a1 = k.y * r * knw[e + 1];
        float a2 = k.z * r * knw[e + 2], a3 = k.w * r * knw[e + 3];
        *reinterpret_cast<__half2*>(&g_kf[ob]) =
            __floats2half2_rn(a0 * co0 - a1 * si0, a0 * si0 + a1 * co0);
        *reinterpret_cast<__half2*>(&g_kf[ob + 2]) =
            __floats2half2_rn(a2 * co1 - a3 * si1, a2 * si1 + a3 * co1);
    }
    {
        float4 v = *reinterpret_cast<const float4*>(&g_vp[base + e]);
        *reinterpret_cast<__half2*>(&g_vf[ob])     = __floats2half2_rn(v.x, v.y);
        *reinterpret_cast<__half2*>(&g_vf[ob + 2]) = __floats2half2_rn(v.z, v.w);
    }
}

// ---------------- Flash attention: 128q tile, 64-key stripes, cp.async x3 -----
// scores arrive in log2 units (log2e folded into q) -> exp2f softmax
#define AKROW 136                        // padded row (halves)
#define ATILE (64 * AKROW * 2)           // 17408 B per K or V tile
#define ASTAGE (2 * ATILE)               // 34816 B
#define ANST 3
#define ASMEM (ANST * ASTAGE)            // 104448 B

__global__ __launch_bounds__(256, 1) void attn_kernel() {
    const int head = blockIdx.y;
    const int qb = blockIdx.x * 128;
    const int tid = threadIdx.x, lane = tid & 31, warp = tid >> 5;
    const int g = lane >> 2, cc2 = (lane & 3) * 2;
    const size_t hb = (size_t)head * NTOK * HD;
    const __half* Qf = g_qf + hb;
    const __half* Kf = g_kf + hb;
    const __half* Vf = g_vf + hb;

    extern __shared__ char adsm[];
    const uint32_t ab = smem_u32(adsm);

    const int krow = (lane >> 3) * 8 + (lane & 7);

    auto issueA = [&](int kt, int s) {
        int kbase = kt * 64;
        #pragma unroll
        for (int j = 0; j < 8; j++) {
            int u = tid + j * 256;
            int t = u >> 10;             // 0 = K, 1 = V
            int uu = u & 1023;
            int row = uu >> 4;
            int c16 = uu & 15;
            const __half* src = t ? Vf : Kf;
            uint32_t dst = ab + s * ASTAGE + t * ATILE + row * (AKROW * 2) + c16 * 16;
            cpasync16(dst, src + (size_t)(kbase + row) * HD + c16 * 8);
        }
        cpcommit();
    };

    const int r0 = qb + warp * 16 + g;
    uint32_t qa[8][4];
    #pragma unroll
    for (int ks = 0; ks < 8; ks++) {
        qa[ks][0] = *reinterpret_cast<const uint32_t*>(&Qf[(size_t)r0 * HD + ks * 16 + cc2]);
        qa[ks][1] = *reinterpret_cast<const uint32_t*>(&Qf[(size_t)(r0 + 8) * HD + ks * 16 + cc2]);
        qa[ks][2] = *reinterpret_cast<const uint32_t*>(&Qf[(size_t)r0 * HD + ks * 16 + cc2 + 8]);
        qa[ks][3] = *reinterpret_cast<const uint32_t*>(&Qf[(size_t)(r0 + 8) * HD + ks * 16 + cc2 + 8]);
    }

    issueA(0, 0);
    issueA(1, 1);

    float o[16][4] = {};
    float m0v = -1e30f, m1v = -1e30f, l0 = 0.f, l1 = 0.f;
    const int NKT = NTOK / 64;   // 64

    for (int kt = 0; kt < NKT; kt++) {
        const int s = kt % ANST;
        if (kt == NKT - 1) cpwait<0>(); else cpwait<1>();
        __syncthreads();
        if (kt + 2 < NKT) issueA(kt + 2, (kt + 2) % ANST);

        const uint32_t skb = ab + s * ASTAGE;
        const uint32_t svb = skb + ATILE;

        float sc[8][4] = {};
        #pragma unroll
        for (int ks = 0; ks < 8; ks++) {
            uint32_t kb0[4], kb1[4], kc0[4], kc1[4];
            ldsm4(kb0[0], kb0[1], kb0[2], kb0[3],
                  skb + (uint32_t)(krow * AKROW + ks * 16) * 2);
            ldsm4(kb1[0], kb1[1], kb1[2], kb1[3],
                  skb + (uint32_t)(krow * AKROW + ks * 16 + 8) * 2);
            ldsm4(kc0[0], kc0[1], kc0[2], kc0[3],
                  skb + (uint32_t)((32 + krow) * AKROW + ks * 16) * 2);
            ldsm4(kc1[0], kc1[1], kc1[2], kc1[3],
                  skb + (uint32_t)((32 + krow) * AKROW + ks * 16 + 8) * 2);
            #pragma unroll
            for (int nf = 0; nf < 4; nf++) {
                mma16816h(sc[nf],     qa[ks], kb0[nf], kb1[nf]);
                mma16816h(sc[nf + 4], qa[ks], kc0[nf], kc1[nf]);
            }
        }

        float mx0 = -1e30f, mx1 = -1e30f;
        #pragma unroll
        for (int nf = 0; nf < 8; nf++) {
            mx0 = fmaxf(mx0, fmaxf(sc[nf][0], sc[nf][1]));
            mx1 = fmaxf(mx1, fmaxf(sc[nf][2], sc[nf][3]));
        }
        mx0 = fmaxf(mx0, __shfl_xor_sync(0xffffffffu, mx0, 1));
        mx0 = fmaxf(mx0, __shfl_xor_sync(0xffffffffu, mx0, 2));
        mx1 = fmaxf(mx1, __shfl_xor_sync(0xffffffffu, mx1, 1));
        mx1 = fmaxf(mx1, __shfl_xor_sync(0xffffffffu, mx1, 2));
        float nm0 = fmaxf(m0v, mx0), nm1 = fmaxf(m1v, mx1);
        float c0 = exp2f(m0v - nm0), c1 = exp2f(m1v - nm1);
        m0v = nm0; m1v = nm1;

        float rs0 = 0.f, rs1 = 0.f;
        #pragma unroll
        for (int nf = 0; nf < 8; nf++) {
            sc[nf][0] = exp2f(sc[nf][0] - nm0); sc[nf][1] = exp2f(sc[nf][1] - nm0);
            sc[nf][2] = exp2f(sc[nf][2] - nm1); sc[nf][3] = exp2f(sc[nf][3] - nm1);
            rs0 += sc[nf][0] + sc[nf][1];
            rs1 += sc[nf][2] + sc[nf][3];
        }
        rs0 += __shfl_xor_sync(0xffffffffu, rs0, 1);
        rs0 += __shfl_xor_sync(0xffffffffu, rs0, 2);
        rs1 += __shfl_xor_sync(0xffffffffu, rs1, 1);
        rs1 += __shfl_xor_sync(0xffffffffu, rs1, 2);
        l0 = l0 * c0 + rs0; l1 = l1 * c1 + rs1;
        #pragma unroll
        for (int nf = 0; nf < 16; nf++) {
            o[nf][0] *= c0; o[nf][1] *= c0; o[nf][2] *= c1; o[nf][3] *= c1;
        }

        uint32_t pa[4][4];
        #pragma unroll
        for (int kk = 0; kk < 4; kk++) {
            pa[kk][0] = packh(sc[2 * kk][0],     sc[2 * kk][1]);
            pa[kk][1] = packh(sc[2 * kk][2],     sc[2 * kk][3]);
            pa[kk][2] = packh(sc[2 * kk + 1][0], sc[2 * kk + 1][1]);
            pa[kk][3] = packh(sc[2 * kk + 1][2], sc[2 * kk + 1][3]);
        }
        #pragma unroll
        for (int kk = 0; kk < 4; kk++) {
            #pragma unroll
            for (int dg = 0; dg < 4; dg++) {
                uint32_t a0 = svb + (uint32_t)((kk * 16 + (lane & 7)) * AKROW
                                               + dg * 32 + (lane >> 3) * 8) * 2;
                uint32_t a1 = svb + (uint32_t)((kk * 16 + 8 + (lane & 7)) * AKROW
                                               + dg * 32 + (lane >> 3) * 8) * 2;
                uint32_t vb0[4], vb1[4];
                ldsm4t(vb0[0], vb0[1], vb0[2], vb0[3], a0);
                ldsm4t(vb1[0], vb1[1], vb1[2], vb1[3], a1);
                #pragma unroll
                for (int j = 0; j < 4; j++)
                    mma16816h(o[dg * 4 + j], pa[kk], vb0[j], vb1[j]);
            }
        }
    }

    float i0 = 1.f / l0, i1 = 1.f / l1;
    #pragma unroll
    for (int nf = 0; nf < 16; nf++) {
        int col = head * HD + nf * 8 + cc2;
        *reinterpret_cast<uint32_t*>(&g_aof[(size_t)r0 * CDIM + col]) =
            packh(o[nf][0] * i0, o[nf][1] * i0);
        *reinterpret_cast<uint32_t*>(&g_aof[(size_t)(r0 + 8) * CDIM + col]) =
            packh(o[nf][2] * i1, o[nf][3] * i1);
    }
}

// ---------------- launch ------------------------------------------------------
extern "C" void kernel_launch(void* const* d_in, const int* in_sizes, int n_in,
                              void* d_out, int out_size) {
    const float* x   = (const float*)d_in[0];
    const float* Wq  = (const float*)d_in[1];
    const float* bq  = (const float*)d_in[2];
    const float* Wk  = (const float*)d_in[3];
    const float* bk  = (const float*)d_in[4];
    const float* Wv  = (const float*)d_in[5];
    const float* bv  = (const float*)d_in[6];
    const float* qnw = (const float*)d_in[7];
    const float* knw = (const float*)d_in[8];
    const float* Wo  = (const float*)d_in[9];
    const float* bo  = (const float*)d_in[10];
    float* out = (float*)d_out;

    cudaFuncSetAttribute(gemm_f16<0>, cudaFuncAttributeMaxDynamicSharedMemorySize, GSMEM);
    cudaFuncSetAttribute(gemm_f16<1>, cudaFuncAttributeMaxDynamicSharedMemorySize, GSMEM);
    cudaFuncSetAttribute(attn_kernel, cudaFuncAttributeMaxDynamicSharedMemorySize, ASMEM);

    const int NTOT = NXE + 4 * NWE;   // 25165824
    cvt_all<<<NTOT / 1024, 256>>>(x, Wq, Wk, Wv, Wo);

    gemm_f16<0><<<dim3(48, 32), 256, GSMEM>>>(bq, bk, bv, nullptr);

    normrope<<<NTOK * HEADS / 4, 128>>>(qnw, knw);

    dim3 agrid(NTOK / 128, HEADS);
    attn_kernel<<<agrid, 256, ASMEM>>>();

    gemm_f16<1><<<dim3(16, 32), 256, GSMEM>>>(bo, nullptr, nullptr, out);
}